// round 1
// baseline (speedup 1.0000x reference)
#include <cuda_runtime.h>
#include <cuda_bf16.h>
#include <math.h>

#define N_SRC1 200000
#define N_TGT1 50000
#define N_TGT2 10000
#define E1 1000000
#define E2 300000
#define F_IN 256
#define F_HID 192
#define F_OUT 128

// ---------------- scratch (device globals; allocation is forbidden) ----------------
__device__ int g_deg1[N_TGT1];
__device__ int g_off1[N_TGT1 + 1];
__device__ int g_pos1[N_TGT1];
__device__ int g_idx1[E1];

__device__ int g_deg2[N_TGT2];
__device__ int g_off2[N_TGT2 + 1];
__device__ int g_pos2[N_TGT2];
__device__ int g_idx2[E2];

__device__ float g_agg1[(size_t)N_TGT1 * F_IN];
__device__ float g_h1[(size_t)N_TGT1 * F_HID];
__device__ float g_agg2[(size_t)N_TGT2 * F_HID];
__device__ float g_h2[(size_t)N_TGT2 * F_HID];
__device__ float g_logits[(size_t)N_TGT2 * F_OUT];

// ---------------- small kernels ----------------
__global__ void zero_deg_kernel() {
    int i = blockIdx.x * blockDim.x + threadIdx.x;
    if (i < N_TGT1) g_deg1[i] = 0;
    if (i < N_TGT2) g_deg2[i] = 0;
}

__global__ void hist_kernel(const int* __restrict__ tgt, int n, int* __restrict__ deg) {
    int i = blockIdx.x * blockDim.x + threadIdx.x;
    if (i < n) atomicAdd(&deg[tgt[i]], 1);
}

// single-block exclusive scan (shuffle-based), also seeds pos[] with offsets
__global__ void scan_kernel(const int* __restrict__ deg, int n,
                            int* __restrict__ off, int* __restrict__ pos) {
    __shared__ int warp_sums[32];
    __shared__ int s_carry;
    int tid = threadIdx.x, lane = tid & 31, wid = tid >> 5;
    if (tid == 0) { s_carry = 0; off[0] = 0; }
    __syncthreads();
    for (int base = 0; base < n; base += blockDim.x) {
        int i = base + tid;
        int v = (i < n) ? deg[i] : 0;
        int sc = v;
        #pragma unroll
        for (int o = 1; o < 32; o <<= 1) {
            int t = __shfl_up_sync(0xFFFFFFFFu, sc, o);
            if (lane >= o) sc += t;
        }
        if (lane == 31) warp_sums[wid] = sc;
        __syncthreads();
        if (wid == 0) {
            int ws = warp_sums[lane];
            #pragma unroll
            for (int o = 1; o < 32; o <<= 1) {
                int t = __shfl_up_sync(0xFFFFFFFFu, ws, o);
                if (lane >= o) ws += t;
            }
            warp_sums[lane] = ws;
        }
        __syncthreads();
        int carry = s_carry;
        int incl = sc + (wid > 0 ? warp_sums[wid - 1] : 0) + carry;
        if (i < n) { off[i + 1] = incl; pos[i] = incl - v; }
        __syncthreads();
        if (tid == blockDim.x - 1) s_carry = incl;
        __syncthreads();
    }
}

__global__ void fill_kernel(const int* __restrict__ src, const int* __restrict__ tgt,
                            int n, int* __restrict__ pos, int* __restrict__ idx) {
    int i = blockIdx.x * blockDim.x + threadIdx.x;
    if (i < n) {
        int p = atomicAdd(&pos[tgt[i]], 1);
        idx[p] = src[i];
    }
}

// ---------------- warp-per-target segment mean (CSR) ----------------
__global__ void agg_kernel(const float* __restrict__ feat, int F,
                           const int* __restrict__ off, const int* __restrict__ idx,
                           float* __restrict__ out, int n_tgt) {
    int w = (blockIdx.x * blockDim.x + threadIdx.x) >> 5;
    int lane = threadIdx.x & 31;
    if (w >= n_tgt) return;
    int beg = off[w], end = off[w + 1];
    int F4 = F >> 2;
    bool two = (lane + 32) < F4;
    float4 a0 = make_float4(0.f, 0.f, 0.f, 0.f);
    float4 a1 = make_float4(0.f, 0.f, 0.f, 0.f);
    for (int e = beg; e < end; e++) {
        const float4* r = (const float4*)(feat + (size_t)idx[e] * F);
        float4 v = r[lane];
        a0.x += v.x; a0.y += v.y; a0.z += v.z; a0.w += v.w;
        if (two) {
            float4 u = r[lane + 32];
            a1.x += u.x; a1.y += u.y; a1.z += u.z; a1.w += u.w;
        }
    }
    int c = end - beg;
    float s = 1.0f / (float)(c > 1 ? c : 1);
    float4* o = (float4*)(out + (size_t)w * F);
    o[lane] = make_float4(a0.x * s, a0.y * s, a0.z * s, a0.w * s);
    if (two) o[lane + 32] = make_float4(a1.x * s, a1.y * s, a1.z * s, a1.w * s);
}

// ---------------- two-stream fused SGEMM: C = act(A1@Wa^T + A2@Wb^T + bias) ----------------
// A row-major [M, lda], W row-major [N, K], C row-major [M, N].
#define GBM 128
#define GBN 64
#define GBK 16

__global__ __launch_bounds__(256) void gemm_kernel(
    const float* __restrict__ A1, int lda1, const float* __restrict__ Wa, int K1,
    const float* __restrict__ A2, int lda2, const float* __restrict__ Wb, int K2,
    const float* __restrict__ bias, float* __restrict__ C, int M, int N,
    int relu_out, int relu_a)
{
    __shared__ float As[GBK][GBM];
    __shared__ float Bs[GBK][GBN];
    int tid = threadIdx.x;
    int tx = tid & 15, ty = tid >> 4;
    int m0 = blockIdx.y * GBM;
    int n0 = blockIdx.x * GBN;

    float acc[8][4];
    #pragma unroll
    for (int i = 0; i < 8; i++)
        #pragma unroll
        for (int j = 0; j < 4; j++) acc[i][j] = 0.f;

    #pragma unroll 1
    for (int s = 0; s < 2; s++) {
        const float* A = s ? A2 : A1;
        const float* W = s ? Wb : Wa;
        int K = s ? K2 : K1;
        int lda = s ? lda2 : lda1;
        if (K == 0) continue;
        #pragma unroll 1
        for (int k0 = 0; k0 < K; k0 += GBK) {
            // A tile: 128 rows x 16 cols, 2 float4 per thread, transposed into As
            #pragma unroll
            for (int p = 0; p < 2; p++) {
                int r = (tid >> 2) + p * 64;
                int c4 = (tid & 3) * 4;
                int gr = m0 + r; if (gr >= M) gr = M - 1;
                float4 v = *(const float4*)(A + (size_t)gr * lda + k0 + c4);
                if (relu_a) {
                    v.x = fmaxf(v.x, 0.f); v.y = fmaxf(v.y, 0.f);
                    v.z = fmaxf(v.z, 0.f); v.w = fmaxf(v.w, 0.f);
                }
                As[c4 + 0][r] = v.x; As[c4 + 1][r] = v.y;
                As[c4 + 2][r] = v.z; As[c4 + 3][r] = v.w;
            }
            // B tile: 64 rows (n) x 16 cols (k)
            {
                int nn = tid >> 2;
                int c4 = (tid & 3) * 4;
                float4 v = *(const float4*)(W + (size_t)(n0 + nn) * K + k0 + c4);
                Bs[c4 + 0][nn] = v.x; Bs[c4 + 1][nn] = v.y;
                Bs[c4 + 2][nn] = v.z; Bs[c4 + 3][nn] = v.w;
            }
            __syncthreads();
            #pragma unroll
            for (int kk = 0; kk < GBK; kk++) {
                float4 a0 = *(const float4*)&As[kk][ty * 8];
                float4 a1 = *(const float4*)&As[kk][ty * 8 + 4];
                float4 b  = *(const float4*)&Bs[kk][tx * 4];
                float a[8] = {a0.x, a0.y, a0.z, a0.w, a1.x, a1.y, a1.z, a1.w};
                float bb[4] = {b.x, b.y, b.z, b.w};
                #pragma unroll
                for (int i = 0; i < 8; i++)
                    #pragma unroll
                    for (int j = 0; j < 4; j++)
                        acc[i][j] = fmaf(a[i], bb[j], acc[i][j]);
            }
            __syncthreads();
        }
    }

    float4 bv = *(const float4*)(bias + n0 + tx * 4);
    #pragma unroll
    for (int i = 0; i < 8; i++) {
        int gr = m0 + ty * 8 + i;
        if (gr < M) {
            float4 o;
            o.x = acc[i][0] + bv.x;
            o.y = acc[i][1] + bv.y;
            o.z = acc[i][2] + bv.z;
            o.w = acc[i][3] + bv.w;
            if (relu_out) {
                o.x = fmaxf(o.x, 0.f); o.y = fmaxf(o.y, 0.f);
                o.z = fmaxf(o.z, 0.f); o.w = fmaxf(o.w, 0.f);
            }
            *(float4*)(C + (size_t)gr * N + n0 + tx * 4) = o;
        }
    }
}

// ---------------- log_softmax over 128 cols, warp per row ----------------
__global__ void logsoftmax_kernel(const float* __restrict__ logits,
                                  float* __restrict__ out, int n) {
    int w = (blockIdx.x * blockDim.x + threadIdx.x) >> 5;
    int lane = threadIdx.x & 31;
    if (w >= n) return;
    float4 v = ((const float4*)(logits + (size_t)w * F_OUT))[lane];
    float m = fmaxf(fmaxf(v.x, v.y), fmaxf(v.z, v.w));
    #pragma unroll
    for (int o = 16; o > 0; o >>= 1) m = fmaxf(m, __shfl_xor_sync(0xFFFFFFFFu, m, o));
    float s = expf(v.x - m) + expf(v.y - m) + expf(v.z - m) + expf(v.w - m);
    #pragma unroll
    for (int o = 16; o > 0; o >>= 1) s += __shfl_xor_sync(0xFFFFFFFFu, s, o);
    float l = m + logf(s);
    float4 o4 = make_float4(v.x - l, v.y - l, v.z - l, v.w - l);
    ((float4*)(out + (size_t)w * F_OUT))[lane] = o4;
}

// ---------------- launch ----------------
extern "C" void kernel_launch(void* const* d_in, const int* in_sizes, int n_in,
                              void* d_out, int out_size) {
    const float* x   = (const float*)d_in[0];
    const int*   ei1 = (const int*)d_in[1];
    const int*   ei2 = (const int*)d_in[2];
    const float* Wl1 = (const float*)d_in[3];
    const float* bl1 = (const float*)d_in[4];
    const float* Wr1 = (const float*)d_in[5];
    const float* Wl2 = (const float*)d_in[6];
    const float* bl2 = (const float*)d_in[7];
    const float* Wr2 = (const float*)d_in[8];
    const float* W1  = (const float*)d_in[9];
    const float* b1  = (const float*)d_in[10];
    const float* W2  = (const float*)d_in[11];
    const float* b2  = (const float*)d_in[12];

    float* out = (float*)d_out;
    float* out_ls  = out;                                 // [10000,128]
    float* out_emb = out + (size_t)N_TGT2 * F_OUT;        // [10000,192]

    int *deg1, *off1, *pos1, *idx1, *deg2, *off2, *pos2, *idx2;
    float *agg1, *h1, *agg2, *h2, *logits;
    cudaGetSymbolAddress((void**)&deg1, g_deg1);
    cudaGetSymbolAddress((void**)&off1, g_off1);
    cudaGetSymbolAddress((void**)&pos1, g_pos1);
    cudaGetSymbolAddress((void**)&idx1, g_idx1);
    cudaGetSymbolAddress((void**)&deg2, g_deg2);
    cudaGetSymbolAddress((void**)&off2, g_off2);
    cudaGetSymbolAddress((void**)&pos2, g_pos2);
    cudaGetSymbolAddress((void**)&idx2, g_idx2);
    cudaGetSymbolAddress((void**)&agg1, g_agg1);
    cudaGetSymbolAddress((void**)&h1, g_h1);
    cudaGetSymbolAddress((void**)&agg2, g_agg2);
    cudaGetSymbolAddress((void**)&h2, g_h2);
    cudaGetSymbolAddress((void**)&logits, g_logits);

    const int* tgt1 = ei1 + E1;
    const int* tgt2 = ei2 + E2;

    // CSR build
    zero_deg_kernel<<<(N_TGT1 + 255) / 256, 256>>>();
    hist_kernel<<<(E1 + 255) / 256, 256>>>(tgt1, E1, deg1);
    hist_kernel<<<(E2 + 255) / 256, 256>>>(tgt2, E2, deg2);
    scan_kernel<<<1, 1024>>>(deg1, N_TGT1, off1, pos1);
    scan_kernel<<<1, 1024>>>(deg2, N_TGT2, off2, pos2);
    fill_kernel<<<(E1 + 255) / 256, 256>>>(ei1, tgt1, E1, pos1, idx1);
    fill_kernel<<<(E2 + 255) / 256, 256>>>(ei2, tgt2, E2, pos2, idx2);

    // Layer 1: agg1 = segment_mean(x[src], tgt1) ; h1 = relu(agg1@Wl1^T + x@Wr1^T + bl1)
    agg_kernel<<<(N_TGT1 * 32 + 255) / 256, 256>>>(x, F_IN, off1, idx1, agg1, N_TGT1);
    {
        dim3 grid(F_HID / GBN, (N_TGT1 + GBM - 1) / GBM);
        gemm_kernel<<<grid, 256>>>(agg1, F_IN, Wl1, F_IN,
                                   x, F_IN, Wr1, F_IN,
                                   bl1, h1, N_TGT1, F_HID, 1, 0);
    }

    // Layer 2: agg2 = segment_mean(h1[src], tgt2) ; h2 = relu(agg2@Wl2^T + h1@Wr2^T + bl2)
    agg_kernel<<<(N_TGT2 * 32 + 255) / 256, 256>>>(h1, F_HID, off2, idx2, agg2, N_TGT2);
    {
        dim3 grid(F_HID / GBN, (N_TGT2 + GBM - 1) / GBM);
        gemm_kernel<<<grid, 256>>>(agg2, F_HID, Wl2, F_HID,
                                   h1, F_HID, Wr2, F_HID,
                                   bl2, h2, N_TGT2, F_HID, 1, 0);
    }

    // embedding = h2@W1^T + b1  -> straight into d_out embedding region
    {
        dim3 grid(F_HID / GBN, (N_TGT2 + GBM - 1) / GBM);
        gemm_kernel<<<grid, 256>>>(h2, F_HID, W1, F_HID,
                                   (const float*)0, 0, (const float*)0, 0,
                                   b1, out_emb, N_TGT2, F_HID, 0, 0);
    }

    // logits = relu(embedding)@W2^T + b2
    {
        dim3 grid(F_OUT / GBN, (N_TGT2 + GBM - 1) / GBM);
        gemm_kernel<<<grid, 256>>>(out_emb, F_HID, W2, F_HID,
                                   (const float*)0, 0, (const float*)0, 0,
                                   b2, logits, N_TGT2, F_OUT, 0, 1);
    }

    // log_softmax
    logsoftmax_kernel<<<(N_TGT2 * 32 + 255) / 256, 256>>>(logits, out_ls, N_TGT2);
}

// round 2
// speedup vs baseline: 1.1383x; 1.1383x over previous
#include <cuda_runtime.h>
#include <cuda_bf16.h>
#include <math.h>

#define N_SRC1 200000
#define N_TGT1 50000
#define N_TGT2 10000
#define E1 1000000
#define E2 300000
#define F_IN 256
#define F_HID 192
#define F_OUT 128

typedef unsigned long long ull;

// ---------------- scratch (device globals; allocation is forbidden) ----------------
__device__ int g_deg1[N_TGT1];
__device__ int g_off1[N_TGT1 + 1];
__device__ int g_pos1[N_TGT1];
__device__ int g_idx1[E1];

__device__ int g_deg2[N_TGT2];
__device__ int g_off2[N_TGT2 + 1];
__device__ int g_pos2[N_TGT2];
__device__ int g_idx2[E2];

__device__ int g_bsum1[256];
__device__ int g_bsum2[256];

__device__ float g_agg1[(size_t)N_TGT1 * F_IN];
__device__ float g_h1[(size_t)N_TGT1 * F_HID];
__device__ float g_agg2[(size_t)N_TGT2 * F_HID];
__device__ float g_logits[(size_t)N_TGT2 * F_OUT];

// ---------------- f32x2 packed math (Blackwell; PTX-only path) ----------------
__device__ __forceinline__ void ffma2(ull& d, ull a, ull b) {
    asm("fma.rn.f32x2 %0, %1, %2, %3;" : "=l"(d) : "l"(a), "l"(b), "l"(d));
}
__device__ __forceinline__ ull pk(float x, float y) {
    ull r; asm("mov.b64 %0, {%1, %2};" : "=l"(r) : "f"(x), "f"(y)); return r;
}
__device__ __forceinline__ void upk(float& x, float& y, ull v) {
    asm("mov.b64 {%0, %1}, %2;" : "=f"(x), "=f"(y) : "l"(v));
}

// ---------------- small kernels ----------------
__global__ void zero_deg_kernel() {
    int i = blockIdx.x * blockDim.x + threadIdx.x;
    if (i < N_TGT1) g_deg1[i] = 0;
    if (i < N_TGT2) g_deg2[i] = 0;
}

__global__ void hist_kernel(const int* __restrict__ tgt, int n, int* __restrict__ deg) {
    int i = blockIdx.x * blockDim.x + threadIdx.x;
    if (i < n) atomicAdd(&deg[tgt[i]], 1);
}

// ---- 3-phase parallel exclusive scan ----
__global__ void scan_block_kernel(const int* __restrict__ deg, int n,
                                  int* __restrict__ off, int* __restrict__ pos,
                                  int* __restrict__ bsum) {
    __shared__ int wsum[16];
    int tid = threadIdx.x, lane = tid & 31, wid = tid >> 5;
    int i = blockIdx.x * 512 + tid;
    int v = (i < n) ? deg[i] : 0;
    int sc = v;
    #pragma unroll
    for (int o = 1; o < 32; o <<= 1) {
        int t = __shfl_up_sync(0xFFFFFFFFu, sc, o);
        if (lane >= o) sc += t;
    }
    if (lane == 31) wsum[wid] = sc;
    __syncthreads();
    if (wid == 0) {
        int ws = (lane < 16) ? wsum[lane] : 0;
        #pragma unroll
        for (int o = 1; o < 16; o <<= 1) {
            int t = __shfl_up_sync(0xFFFFFFFFu, ws, o);
            if (lane >= o) ws += t;
        }
        if (lane < 16) wsum[lane] = ws;
    }
    __syncthreads();
    int incl = sc + (wid ? wsum[wid - 1] : 0);
    if (i < n) { off[i + 1] = incl; pos[i] = incl - v; }
    if (tid == 511) bsum[blockIdx.x] = incl;
}

__global__ void scan_bsum_kernel(int* __restrict__ bsum, int nb, int* __restrict__ off) {
    __shared__ int s[128];
    int tid = threadIdx.x;
    int v = (tid < nb) ? bsum[tid] : 0;
    s[tid] = v;
    __syncthreads();
    #pragma unroll
    for (int o = 1; o < 128; o <<= 1) {
        int t = (tid >= o) ? s[tid - o] : 0;
        __syncthreads();
        s[tid] += t;
        __syncthreads();
    }
    if (tid < nb) bsum[tid] = s[tid] - v;  // exclusive
    if (tid == 0) off[0] = 0;
}

__global__ void scan_add_kernel(int n, int* __restrict__ off, int* __restrict__ pos,
                                const int* __restrict__ bsum) {
    int i = blockIdx.x * 512 + threadIdx.x;
    if (i < n) {
        int a = bsum[blockIdx.x];
        off[i + 1] += a;
        pos[i] += a;
    }
}

__global__ void fill_kernel(const int* __restrict__ src, const int* __restrict__ tgt,
                            int n, int* __restrict__ pos, int* __restrict__ idx) {
    int i = blockIdx.x * blockDim.x + threadIdx.x;
    if (i < n) {
        int p = atomicAdd(&pos[tgt[i]], 1);
        idx[p] = src[i];
    }
}

// ---------------- warp-per-target segment mean (CSR) ----------------
__global__ void agg_kernel(const float* __restrict__ feat, int F,
                           const int* __restrict__ off, const int* __restrict__ idx,
                           float* __restrict__ out, int n_tgt) {
    int w = (blockIdx.x * blockDim.x + threadIdx.x) >> 5;
    int lane = threadIdx.x & 31;
    if (w >= n_tgt) return;
    int beg = off[w], end = off[w + 1];
    int F4 = F >> 2;
    bool two = (lane + 32) < F4;
    float4 a0 = make_float4(0.f, 0.f, 0.f, 0.f);
    float4 a1 = make_float4(0.f, 0.f, 0.f, 0.f);
    for (int e = beg; e < end; e++) {
        const float4* r = (const float4*)(feat + (size_t)idx[e] * F);
        float4 v = __ldg(&r[lane]);
        a0.x += v.x; a0.y += v.y; a0.z += v.z; a0.w += v.w;
        if (two) {
            float4 u = __ldg(&r[lane + 32]);
            a1.x += u.x; a1.y += u.y; a1.z += u.z; a1.w += u.w;
        }
    }
    int c = end - beg;
    float s = 1.0f / (float)(c > 1 ? c : 1);
    float4* o = (float4*)(out + (size_t)w * F);
    o[lane] = make_float4(a0.x * s, a0.y * s, a0.z * s, a0.w * s);
    if (two) o[lane + 32] = make_float4(a1.x * s, a1.y * s, a1.z * s, a1.w * s);
}

// ---------------- two-stream fused SGEMM, f32x2 + double-buffered smem ----------------
#define TM 128
#define TN 64
#define TK 16
#define PADA 4
#define PADB 4

__global__ __launch_bounds__(128) void gemm_kernel(
    const float* __restrict__ A1, int lda1, const float* __restrict__ Wa, int K1,
    const float* __restrict__ A2, int lda2, const float* __restrict__ Wb, int K2,
    const float* __restrict__ bias, float* __restrict__ C, int M, int N,
    int relu_out, int relu_a)
{
    __shared__ float As[2][TK][TM + PADA];
    __shared__ float Bs[2][TK][TN + PADB];
    int tid = threadIdx.x;
    int m0 = blockIdx.y * TM;
    int n0 = blockIdx.x * TN;
    int tx = tid & 7;
    int ty = tid >> 3;
    int lr = tid >> 2;
    int lc = (tid & 3) * 4;

    ull acc[8][4];
    #pragma unroll
    for (int i = 0; i < 8; i++)
        #pragma unroll
        for (int j = 0; j < 4; j++) acc[i][j] = 0ULL;

    float4 ra[4], rb[2];
    int iters = (K1 + K2) / TK;

    auto LOAD = [&](int t) {
        int kv = t * TK;
        const float* A; const float* W; int lda, kk, wk;
        if (kv < K1) { A = A1; W = Wa; lda = lda1; kk = kv; wk = K1; }
        else         { A = A2; W = Wb; lda = lda2; kk = kv - K1; wk = K2; }
        #pragma unroll
        for (int p = 0; p < 4; p++) {
            int gr = m0 + lr + p * 32; if (gr >= M) gr = M - 1;
            float4 v = *(const float4*)(A + (size_t)gr * lda + kk + lc);
            if (relu_a) {
                v.x = fmaxf(v.x, 0.f); v.y = fmaxf(v.y, 0.f);
                v.z = fmaxf(v.z, 0.f); v.w = fmaxf(v.w, 0.f);
            }
            ra[p] = v;
        }
        #pragma unroll
        for (int p = 0; p < 2; p++) {
            int nn = n0 + lr + p * 32;
            rb[p] = *(const float4*)(W + (size_t)nn * wk + kk + lc);
        }
    };
    auto STORE = [&](int buf) {
        #pragma unroll
        for (int p = 0; p < 4; p++) {
            int r = lr + p * 32;
            As[buf][lc + 0][r] = ra[p].x; As[buf][lc + 1][r] = ra[p].y;
            As[buf][lc + 2][r] = ra[p].z; As[buf][lc + 3][r] = ra[p].w;
        }
        #pragma unroll
        for (int p = 0; p < 2; p++) {
            int r = lr + p * 32;
            Bs[buf][lc + 0][r] = rb[p].x; Bs[buf][lc + 1][r] = rb[p].y;
            Bs[buf][lc + 2][r] = rb[p].z; Bs[buf][lc + 3][r] = rb[p].w;
        }
    };

    LOAD(0);
    STORE(0);
    __syncthreads();

    #pragma unroll 1
    for (int t = 0; t < iters; t++) {
        if (t + 1 < iters) LOAD(t + 1);
        int cur = t & 1;
        #pragma unroll
        for (int kk = 0; kk < TK; kk++) {
            float4 b0 = *(const float4*)&Bs[cur][kk][tx * 8];
            float4 b1 = *(const float4*)&Bs[cur][kk][tx * 8 + 4];
            float4 a0 = *(const float4*)&As[cur][kk][ty * 8];
            float4 a1 = *(const float4*)&As[cur][kk][ty * 8 + 4];
            ull bp0 = pk(b0.x, b0.y), bp1 = pk(b0.z, b0.w);
            ull bp2 = pk(b1.x, b1.y), bp3 = pk(b1.z, b1.w);
            float av[8] = {a0.x, a0.y, a0.z, a0.w, a1.x, a1.y, a1.z, a1.w};
            #pragma unroll
            for (int i = 0; i < 8; i++) {
                ull ad = pk(av[i], av[i]);
                ffma2(acc[i][0], ad, bp0);
                ffma2(acc[i][1], ad, bp1);
                ffma2(acc[i][2], ad, bp2);
                ffma2(acc[i][3], ad, bp3);
            }
        }
        if (t + 1 < iters) {
            STORE((t + 1) & 1);
            __syncthreads();
        }
    }

    float4 bv0 = *(const float4*)(bias + n0 + tx * 8);
    float4 bv1 = *(const float4*)(bias + n0 + tx * 8 + 4);
    float bb[8] = {bv0.x, bv0.y, bv0.z, bv0.w, bv1.x, bv1.y, bv1.z, bv1.w};
    #pragma unroll
    for (int i = 0; i < 8; i++) {
        int gr = m0 + ty * 8 + i;
        if (gr < M) {
            float o[8];
            upk(o[0], o[1], acc[i][0]);
            upk(o[2], o[3], acc[i][1]);
            upk(o[4], o[5], acc[i][2]);
            upk(o[6], o[7], acc[i][3]);
            #pragma unroll
            for (int j = 0; j < 8; j++) {
                o[j] += bb[j];
                if (relu_out) o[j] = fmaxf(o[j], 0.f);
            }
            float* cp = C + (size_t)gr * N + n0 + tx * 8;
            *(float4*)cp       = make_float4(o[0], o[1], o[2], o[3]);
            *(float4*)(cp + 4) = make_float4(o[4], o[5], o[6], o[7]);
        }
    }
}

// ---------------- log_softmax over 128 cols, warp per row ----------------
__global__ void logsoftmax_kernel(const float* __restrict__ logits,
                                  float* __restrict__ out, int n) {
    int w = (blockIdx.x * blockDim.x + threadIdx.x) >> 5;
    int lane = threadIdx.x & 31;
    if (w >= n) return;
    float4 v = ((const float4*)(logits + (size_t)w * F_OUT))[lane];
    float m = fmaxf(fmaxf(v.x, v.y), fmaxf(v.z, v.w));
    #pragma unroll
    for (int o = 16; o > 0; o >>= 1) m = fmaxf(m, __shfl_xor_sync(0xFFFFFFFFu, m, o));
    float s = expf(v.x - m) + expf(v.y - m) + expf(v.z - m) + expf(v.w - m);
    #pragma unroll
    for (int o = 16; o > 0; o >>= 1) s += __shfl_xor_sync(0xFFFFFFFFu, s, o);
    float l = m + logf(s);
    float4 o4 = make_float4(v.x - l, v.y - l, v.z - l, v.w - l);
    ((float4*)(out + (size_t)w * F_OUT))[lane] = o4;
}

// ---------------- launch ----------------
extern "C" void kernel_launch(void* const* d_in, const int* in_sizes, int n_in,
                              void* d_out, int out_size) {
    const float* x   = (const float*)d_in[0];
    const int*   ei1 = (const int*)d_in[1];
    const int*   ei2 = (const int*)d_in[2];
    const float* Wl1 = (const float*)d_in[3];
    const float* bl1 = (const float*)d_in[4];
    const float* Wr1 = (const float*)d_in[5];
    const float* Wl2 = (const float*)d_in[6];
    const float* bl2 = (const float*)d_in[7];
    const float* Wr2 = (const float*)d_in[8];
    const float* W1  = (const float*)d_in[9];
    const float* b1  = (const float*)d_in[10];
    const float* W2  = (const float*)d_in[11];
    const float* b2  = (const float*)d_in[12];

    float* out = (float*)d_out;
    float* out_ls  = out;                           // [10000,128]
    float* out_emb = out + (size_t)N_TGT2 * F_OUT;  // [10000,192]

    int *deg1, *off1, *pos1, *idx1, *deg2, *off2, *pos2, *idx2, *bsum1, *bsum2;
    float *agg1, *h1, *agg2, *logits;
    cudaGetSymbolAddress((void**)&deg1, g_deg1);
    cudaGetSymbolAddress((void**)&off1, g_off1);
    cudaGetSymbolAddress((void**)&pos1, g_pos1);
    cudaGetSymbolAddress((void**)&idx1, g_idx1);
    cudaGetSymbolAddress((void**)&deg2, g_deg2);
    cudaGetSymbolAddress((void**)&off2, g_off2);
    cudaGetSymbolAddress((void**)&pos2, g_pos2);
    cudaGetSymbolAddress((void**)&idx2, g_idx2);
    cudaGetSymbolAddress((void**)&bsum1, g_bsum1);
    cudaGetSymbolAddress((void**)&bsum2, g_bsum2);
    cudaGetSymbolAddress((void**)&agg1, g_agg1);
    cudaGetSymbolAddress((void**)&h1, g_h1);
    cudaGetSymbolAddress((void**)&agg2, g_agg2);
    cudaGetSymbolAddress((void**)&logits, g_logits);

    const int* tgt1 = ei1 + E1;
    const int* tgt2 = ei2 + E2;

    int nb1 = (N_TGT1 + 511) / 512;  // 98
    int nb2 = (N_TGT2 + 511) / 512;  // 20

    // CSR build
    zero_deg_kernel<<<(N_TGT1 + 255) / 256, 256>>>();
    hist_kernel<<<(E1 + 255) / 256, 256>>>(tgt1, E1, deg1);
    hist_kernel<<<(E2 + 255) / 256, 256>>>(tgt2, E2, deg2);
    scan_block_kernel<<<nb1, 512>>>(deg1, N_TGT1, off1, pos1, bsum1);
    scan_block_kernel<<<nb2, 512>>>(deg2, N_TGT2, off2, pos2, bsum2);
    scan_bsum_kernel<<<1, 128>>>(bsum1, nb1, off1);
    scan_bsum_kernel<<<1, 128>>>(bsum2, nb2, off2);
    scan_add_kernel<<<nb1, 512>>>(N_TGT1, off1, pos1, bsum1);
    scan_add_kernel<<<nb2, 512>>>(N_TGT2, off2, pos2, bsum2);
    fill_kernel<<<(E1 + 255) / 256, 256>>>(ei1, tgt1, E1, pos1, idx1);
    fill_kernel<<<(E2 + 255) / 256, 256>>>(ei2, tgt2, E2, pos2, idx2);

    // Layer 1: h1 = relu(agg1@Wl1^T + x@Wr1^T + bl1)
    agg_kernel<<<(N_TGT1 * 32 + 255) / 256, 256>>>(x, F_IN, off1, idx1, agg1, N_TGT1);
    {
        dim3 grid(F_HID / TN, (N_TGT1 + TM - 1) / TM);
        gemm_kernel<<<grid, 128>>>(agg1, F_IN, Wl1, F_IN,
                                   x, F_IN, Wr1, F_IN,
                                   bl1, h1, N_TGT1, F_HID, 1, 0);
    }

    // Layer 2: h2 = relu(agg2@Wl2^T + h1@Wr2^T + bl2)  (h2 reuses g_agg1, free now)
    agg_kernel<<<(N_TGT2 * 32 + 255) / 256, 256>>>(h1, F_HID, off2, idx2, agg2, N_TGT2);
    float* h2 = agg1;
    {
        dim3 grid(F_HID / TN, (N_TGT2 + TM - 1) / TM);
        gemm_kernel<<<grid, 128>>>(agg2, F_HID, Wl2, F_HID,
                                   h1, F_HID, Wr2, F_HID,
                                   bl2, h2, N_TGT2, F_HID, 1, 0);
    }

    // embedding = h2@W1^T + b1 -> d_out embedding region
    {
        dim3 grid(F_HID / TN, (N_TGT2 + TM - 1) / TM);
        gemm_kernel<<<grid, 128>>>(h2, F_HID, W1, F_HID,
                                   (const float*)0, 0, (const float*)0, 0,
                                   b1, out_emb, N_TGT2, F_HID, 0, 0);
    }

    // logits = relu(embedding)@W2^T + b2
    {
        dim3 grid(F_OUT / TN, (N_TGT2 + TM - 1) / TM);
        gemm_kernel<<<grid, 128>>>(out_emb, F_HID, W2, F_HID,
                                   (const float*)0, 0, (const float*)0, 0,
                                   b2, logits, N_TGT2, F_OUT, 0, 1);
    }

    // log_softmax
    logsoftmax_kernel<<<(N_TGT2 * 32 + 255) / 256, 256>>>(logits, out_ls, N_TGT2);
}

// round 4
// speedup vs baseline: 1.4058x; 1.2350x over previous
#include <cuda_runtime.h>
#include <cuda_bf16.h>
#include <math.h>
#include <stdint.h>

#define N_SRC1 200000
#define N_TGT1 50000
#define N_TGT2 10000
#define E1 1000000
#define E2 300000
#define F_IN 256
#define F_HID 192
#define F_OUT 128

typedef unsigned long long ull;

// ---------------- scratch (device globals; allocation is forbidden) ----------------
__device__ int g_deg1[N_TGT1];
__device__ int g_off1[N_TGT1 + 1];
__device__ int g_pos1[N_TGT1];
__device__ int g_idx1[E1];

__device__ int g_deg2[N_TGT2];
__device__ int g_off2[N_TGT2 + 1];
__device__ int g_pos2[N_TGT2];
__device__ int g_idx2[E2];

__device__ int g_bsum1[256];
__device__ int g_bsum2[256];

// bf16 split operands for layer-1 tensor GEMM: A = [agg1 | x[:50000]] (K=512)
__device__ __nv_bfloat16 g_ahi[(size_t)N_TGT1 * 512];
__device__ __nv_bfloat16 g_alo[(size_t)N_TGT1 * 512];
__device__ __nv_bfloat16 g_whi[(size_t)F_HID * 512];
__device__ __nv_bfloat16 g_wlo[(size_t)F_HID * 512];

__device__ float g_h1[(size_t)N_TGT1 * F_HID];
__device__ float g_agg2[(size_t)N_TGT2 * F_HID];
__device__ float g_h2[(size_t)N_TGT2 * F_HID];
__device__ float g_logits[(size_t)N_TGT2 * F_OUT];

// ---------------- f32x2 packed math ----------------
__device__ __forceinline__ void ffma2(ull& d, ull a, ull b) {
    asm("fma.rn.f32x2 %0, %1, %2, %3;" : "=l"(d) : "l"(a), "l"(b), "l"(d));
}
__device__ __forceinline__ ull pk(float x, float y) {
    ull r; asm("mov.b64 %0, {%1, %2};" : "=l"(r) : "f"(x), "f"(y)); return r;
}
__device__ __forceinline__ void upk(float& x, float& y, ull v) {
    asm("mov.b64 {%0, %1}, %2;" : "=f"(x), "=f"(y) : "l"(v));
}

// ---------------- bf16 split helpers ----------------
__device__ __forceinline__ void split1(float a, __nv_bfloat16& h, __nv_bfloat16& l) {
    h = __float2bfloat16_rn(a);
    l = __float2bfloat16_rn(a - __bfloat162float(h));
}

// ---------------- small kernels ----------------
__global__ void zero_deg_kernel() {
    int i = blockIdx.x * blockDim.x + threadIdx.x;
    if (i < N_TGT1) g_deg1[i] = 0;
    if (i < N_TGT2) g_deg2[i] = 0;
}

__global__ void hist_kernel(const int* __restrict__ tgt, int n, int* __restrict__ deg) {
    int i = blockIdx.x * blockDim.x + threadIdx.x;
    if (i < n) atomicAdd(&deg[tgt[i]], 1);
}

__global__ void scan_block_kernel(const int* __restrict__ deg, int n,
                                  int* __restrict__ off, int* __restrict__ pos,
                                  int* __restrict__ bsum) {
    __shared__ int wsum[16];
    int tid = threadIdx.x, lane = tid & 31, wid = tid >> 5;
    int i = blockIdx.x * 512 + tid;
    int v = (i < n) ? deg[i] : 0;
    int sc = v;
    #pragma unroll
    for (int o = 1; o < 32; o <<= 1) {
        int t = __shfl_up_sync(0xFFFFFFFFu, sc, o);
        if (lane >= o) sc += t;
    }
    if (lane == 31) wsum[wid] = sc;
    __syncthreads();
    if (wid == 0) {
        int ws = (lane < 16) ? wsum[lane] : 0;
        #pragma unroll
        for (int o = 1; o < 16; o <<= 1) {
            int t = __shfl_up_sync(0xFFFFFFFFu, ws, o);
            if (lane >= o) ws += t;
        }
        if (lane < 16) wsum[lane] = ws;
    }
    __syncthreads();
    int incl = sc + (wid ? wsum[wid - 1] : 0);
    if (i < n) { off[i + 1] = incl; pos[i] = incl - v; }
    if (tid == 511) bsum[blockIdx.x] = incl;
}

__global__ void scan_bsum_kernel(int* __restrict__ bsum, int nb, int* __restrict__ off) {
    __shared__ int s[128];
    int tid = threadIdx.x;
    int v = (tid < nb) ? bsum[tid] : 0;
    s[tid] = v;
    __syncthreads();
    #pragma unroll
    for (int o = 1; o < 128; o <<= 1) {
        int t = (tid >= o) ? s[tid - o] : 0;
        __syncthreads();
        s[tid] += t;
        __syncthreads();
    }
    if (tid < nb) bsum[tid] = s[tid] - v;
    if (tid == 0) off[0] = 0;
}

__global__ void scan_add_kernel(int n, int* __restrict__ off, int* __restrict__ pos,
                                const int* __restrict__ bsum) {
    int i = blockIdx.x * 512 + threadIdx.x;
    if (i < n) {
        int a = bsum[blockIdx.x];
        off[i + 1] += a;
        pos[i] += a;
    }
}

__global__ void fill_kernel(const int* __restrict__ src, const int* __restrict__ tgt,
                            int n, int* __restrict__ pos, int* __restrict__ idx) {
    int i = blockIdx.x * blockDim.x + threadIdx.x;
    if (i < n) {
        int p = atomicAdd(&pos[tgt[i]], 1);
        idx[p] = src[i];
    }
}

// ---------------- fp32 -> bf16 hi/lo split convert ----------------
__global__ void convert_split_kernel(const float* __restrict__ in, int in_lda,
                                     __nv_bfloat16* __restrict__ hi,
                                     __nv_bfloat16* __restrict__ lo,
                                     int out_lda, int out_col0,
                                     int rows, int cols) {
    int i = blockIdx.x * blockDim.x + threadIdx.x;
    int c4n = cols >> 2;
    if (i >= rows * c4n) return;
    int r = i / c4n, c = (i % c4n) << 2;
    float4 v = *(const float4*)(in + (size_t)r * in_lda + c);
    __nv_bfloat16 h0, h1, h2, h3, l0, l1, l2, l3;
    split1(v.x, h0, l0); split1(v.y, h1, l1);
    split1(v.z, h2, l2); split1(v.w, h3, l3);
    size_t o = (size_t)r * out_lda + out_col0 + c;
    *(__nv_bfloat162*)(hi + o)     = __nv_bfloat162(h0, h1);
    *(__nv_bfloat162*)(hi + o + 2) = __nv_bfloat162(h2, h3);
    *(__nv_bfloat162*)(lo + o)     = __nv_bfloat162(l0, l1);
    *(__nv_bfloat162*)(lo + o + 2) = __nv_bfloat162(l2, l3);
}

// ---------------- warp-per-target segment mean, writes bf16 split (F=256) ----------------
__global__ void agg_split_kernel(const float* __restrict__ feat,
                                 const int* __restrict__ off, const int* __restrict__ idx,
                                 __nv_bfloat16* __restrict__ hi,
                                 __nv_bfloat16* __restrict__ lo,
                                 int out_lda, int n_tgt) {
    int w = (blockIdx.x * blockDim.x + threadIdx.x) >> 5;
    int lane = threadIdx.x & 31;
    if (w >= n_tgt) return;
    int beg = off[w], end = off[w + 1];
    float4 a0 = make_float4(0.f, 0.f, 0.f, 0.f);
    float4 a1 = make_float4(0.f, 0.f, 0.f, 0.f);
    for (int e = beg; e < end; e++) {
        const float4* r = (const float4*)(feat + (size_t)idx[e] * F_IN);
        float4 v = __ldg(&r[lane]);
        a0.x += v.x; a0.y += v.y; a0.z += v.z; a0.w += v.w;
        float4 u = __ldg(&r[lane + 32]);
        a1.x += u.x; a1.y += u.y; a1.z += u.z; a1.w += u.w;
    }
    int c = end - beg;
    float s = 1.0f / (float)(c > 1 ? c : 1);
    a0.x *= s; a0.y *= s; a0.z *= s; a0.w *= s;
    a1.x *= s; a1.y *= s; a1.z *= s; a1.w *= s;
    __nv_bfloat16 h[8], l[8];
    split1(a0.x, h[0], l[0]); split1(a0.y, h[1], l[1]);
    split1(a0.z, h[2], l[2]); split1(a0.w, h[3], l[3]);
    split1(a1.x, h[4], l[4]); split1(a1.y, h[5], l[5]);
    split1(a1.z, h[6], l[6]); split1(a1.w, h[7], l[7]);
    size_t o0 = (size_t)w * out_lda + lane * 4;
    size_t o1 = (size_t)w * out_lda + (lane + 32) * 4;
    *(__nv_bfloat162*)(hi + o0)     = __nv_bfloat162(h[0], h[1]);
    *(__nv_bfloat162*)(hi + o0 + 2) = __nv_bfloat162(h[2], h[3]);
    *(__nv_bfloat162*)(hi + o1)     = __nv_bfloat162(h[4], h[5]);
    *(__nv_bfloat162*)(hi + o1 + 2) = __nv_bfloat162(h[6], h[7]);
    *(__nv_bfloat162*)(lo + o0)     = __nv_bfloat162(l[0], l[1]);
    *(__nv_bfloat162*)(lo + o0 + 2) = __nv_bfloat162(l[2], l[3]);
    *(__nv_bfloat162*)(lo + o1)     = __nv_bfloat162(l[4], l[5]);
    *(__nv_bfloat162*)(lo + o1 + 2) = __nv_bfloat162(l[6], l[7]);
}

// ---------------- fp32 segment mean (layer 2, F=192) ----------------
__global__ void agg_kernel(const float* __restrict__ feat, int F,
                           const int* __restrict__ off, const int* __restrict__ idx,
                           float* __restrict__ out, int n_tgt) {
    int w = (blockIdx.x * blockDim.x + threadIdx.x) >> 5;
    int lane = threadIdx.x & 31;
    if (w >= n_tgt) return;
    int beg = off[w], end = off[w + 1];
    int F4 = F >> 2;
    bool two = (lane + 32) < F4;
    float4 a0 = make_float4(0.f, 0.f, 0.f, 0.f);
    float4 a1 = make_float4(0.f, 0.f, 0.f, 0.f);
    for (int e = beg; e < end; e++) {
        const float4* r = (const float4*)(feat + (size_t)idx[e] * F);
        float4 v = __ldg(&r[lane]);
        a0.x += v.x; a0.y += v.y; a0.z += v.z; a0.w += v.w;
        if (two) {
            float4 u = __ldg(&r[lane + 32]);
            a1.x += u.x; a1.y += u.y; a1.z += u.z; a1.w += u.w;
        }
    }
    int c = end - beg;
    float s = 1.0f / (float)(c > 1 ? c : 1);
    float4* o = (float4*)(out + (size_t)w * F);
    o[lane] = make_float4(a0.x * s, a0.y * s, a0.z * s, a0.w * s);
    if (two) o[lane + 32] = make_float4(a1.x * s, a1.y * s, a1.z * s, a1.w * s);
}

// ================= mma.sync bf16 split GEMM: C[M,192] = relu(A@W^T + bias) =================
// A: [M,512] bf16 hi/lo row-major. W: [192,512] bf16 hi/lo row-major.
// Block: 128M x 192N, 256 threads (8 warps, 4m x 2n, warp tile 32x96).
// K chunks of 32, cp.async double-buffered. smem rows padded to 80B (conflict-free).
#define MK 512
#define MN 192
#define MKC 32
#define MNCH (MK / MKC)     // 16 chunks
#define ROWB 80             // bytes per smem row (32 bf16 + 8 pad)
#define SA_HI 0
#define SA_LO (128 * ROWB)            // 10240
#define SB_HI (2 * 128 * ROWB)        // 20480
#define SB_LO (2 * 128 * ROWB + 192 * ROWB)  // 35840
#define BUFSZ (2 * 128 * ROWB + 2 * 192 * ROWB)  // 51200
#define MMA_SMEM (2 * BUFSZ)          // 102400

__device__ __forceinline__ uint32_t smem_u32(const void* p) {
    uint32_t a;
    asm("{ .reg .u64 t; cvta.to.shared.u64 t, %1; cvt.u32.u64 %0, t; }" : "=r"(a) : "l"(p));
    return a;
}
__device__ __forceinline__ void cp16(uint32_t s, const void* g) {
    asm volatile("cp.async.cg.shared.global [%0], [%1], 16;" :: "r"(s), "l"(g));
}
__device__ __forceinline__ void cp_commit() {
    asm volatile("cp.async.commit_group;");
}
__device__ __forceinline__ void cp_wait1() {
    asm volatile("cp.async.wait_group 1;");
}
__device__ __forceinline__ void ldm4(uint32_t* r, uint32_t a) {
    asm volatile("ldmatrix.sync.aligned.m8n8.x4.shared.b16 {%0,%1,%2,%3}, [%4];"
                 : "=r"(r[0]), "=r"(r[1]), "=r"(r[2]), "=r"(r[3]) : "r"(a));
}
__device__ __forceinline__ void mma_bf16(float* c, const uint32_t* a, uint32_t b0, uint32_t b1) {
    asm volatile("mma.sync.aligned.m16n8k16.row.col.f32.bf16.bf16.f32 "
                 "{%0,%1,%2,%3},{%4,%5,%6,%7},{%8,%9},{%0,%1,%2,%3};"
                 : "+f"(c[0]), "+f"(c[1]), "+f"(c[2]), "+f"(c[3])
                 : "r"(a[0]), "r"(a[1]), "r"(a[2]), "r"(a[3]), "r"(b0), "r"(b1));
}

__global__ __launch_bounds__(256) void mmagemm_kernel(
    const __nv_bfloat16* __restrict__ ahi, const __nv_bfloat16* __restrict__ alo,
    const __nv_bfloat16* __restrict__ whi, const __nv_bfloat16* __restrict__ wlo,
    const float* __restrict__ bias, float* __restrict__ C, int M, int relu_out)
{
    extern __shared__ char sm[];
    uint32_t smb = smem_u32(sm);
    int tid = threadIdx.x;
    int w = tid >> 5, lane = tid & 31;
    int m0 = blockIdx.x * 128;
    int wm = (w >> 1) * 32;        // warp m offset
    int wn = (w & 1) * 96;         // warp n offset

    float acc[2][12][4];
    #pragma unroll
    for (int i = 0; i < 2; i++)
        #pragma unroll
        for (int j = 0; j < 12; j++)
            #pragma unroll
            for (int k = 0; k < 4; k++) acc[i][j][k] = 0.f;

    // cp.async task decomposition
    int arow = tid >> 2;           // 0..63 base; A has 128 rows -> 2 iters
    int aseg = (tid & 3) * 16;     // byte seg within row (4 x 16B)
    int asegk = (tid & 3) * 8;     // bf16 elems

    auto load_chunk = [&](int c) {
        int k0 = c * MKC;
        uint32_t base = smb + (c & 1) * BUFSZ;
        #pragma unroll
        for (int i = 0; i < 2; i++) {
            int row = arow + i * 64;
            int gr = m0 + row; if (gr >= M) gr = M - 1;
            size_t go = (size_t)gr * MK + k0 + asegk;
            uint32_t so = row * ROWB + aseg;
            cp16(base + SA_HI + so, ahi + go);
            cp16(base + SA_LO + so, alo + go);
        }
        #pragma unroll
        for (int i = 0; i < 3; i++) {
            int row = arow + i * 64;   // 0..191
            size_t go = (size_t)row * MK + k0 + asegk;
            uint32_t so = row * ROWB + aseg;
            cp16(base + SB_HI + so, whi + go);
            cp16(base + SB_LO + so, wlo + go);
        }
    };

    // ldmatrix per-lane row addressing
    int grp = lane >> 3, lr = lane & 7;
    int a_row_off = lr + (grp & 1) * 8;        // within m16 tile
    int a_k_off = (grp >> 1) * 8;              // k base within k16
    int b_row_off = (grp & 2) * 4 + lr;        // within n16 pair
    int b_k_off = (grp & 1) * 8;

    load_chunk(0);
    cp_commit();

    #pragma unroll 1
    for (int c = 0; c < MNCH; c++) {
        if (c + 1 < MNCH) load_chunk(c + 1);
        cp_commit();
        cp_wait1();
        __syncthreads();

        uint32_t base = smb + (c & 1) * BUFSZ;
        #pragma unroll
        for (int s = 0; s < 2; s++) {
            uint32_t ah[2][4], al[2][4];
            #pragma unroll
            for (int mt = 0; mt < 2; mt++) {
                uint32_t ra = (wm + mt * 16 + a_row_off) * ROWB + (s * 16 + a_k_off) * 2;
                ldm4(ah[mt], base + SA_HI + ra);
                ldm4(al[mt], base + SA_LO + ra);
            }
            #pragma unroll
            for (int j = 0; j < 6; j++) {
                uint32_t rb = (wn + j * 16 + b_row_off) * ROWB + (s * 16 + b_k_off) * 2;
                uint32_t bh[4], bl[4];
                ldm4(bh, base + SB_HI + rb);
                ldm4(bl, base + SB_LO + rb);
                #pragma unroll
                for (int mt = 0; mt < 2; mt++) {
                    mma_bf16(acc[mt][2 * j],     ah[mt], bh[0], bh[1]);
                    mma_bf16(acc[mt][2 * j],     ah[mt], bl[0], bl[1]);
                    mma_bf16(acc[mt][2 * j],     al[mt], bh[0], bh[1]);
                    mma_bf16(acc[mt][2 * j + 1], ah[mt], bh[2], bh[3]);
                    mma_bf16(acc[mt][2 * j + 1], ah[mt], bl[2], bl[3]);
                    mma_bf16(acc[mt][2 * j + 1], al[mt], bh[2], bh[3]);
                }
            }
        }
        __syncthreads();
    }

    // epilogue
    int g = lane >> 2, t = lane & 3;
    #pragma unroll
    for (int mt = 0; mt < 2; mt++) {
        #pragma unroll
        for (int j = 0; j < 12; j++) {
            int col = wn + j * 8 + 2 * t;
            float2 bv = *(const float2*)(bias + col);
            int r0 = m0 + wm + mt * 16 + g;
            float o0 = acc[mt][j][0] + bv.x;
            float o1 = acc[mt][j][1] + bv.y;
            float o2 = acc[mt][j][2] + bv.x;
            float o3 = acc[mt][j][3] + bv.y;
            if (relu_out) {
                o0 = fmaxf(o0, 0.f); o1 = fmaxf(o1, 0.f);
                o2 = fmaxf(o2, 0.f); o3 = fmaxf(o3, 0.f);
            }
            if (r0 < M)     *(float2*)(C + (size_t)r0 * MN + col)       = make_float2(o0, o1);
            if (r0 + 8 < M) *(float2*)(C + (size_t)(r0 + 8) * MN + col) = make_float2(o2, o3);
        }
    }
}

// ---------------- two-stream fused SGEMM, f32x2 (layers 2-4) ----------------
#define TM 128
#define TN 64
#define TK 16
#define PADA 4
#define PADB 4

__global__ __launch_bounds__(128) void gemm_kernel(
    const float* __restrict__ A1, int lda1, const float* __restrict__ Wa, int K1,
    const float* __restrict__ A2, int lda2, const float* __restrict__ Wb, int K2,
    const float* __restrict__ bias, float* __restrict__ C, int M, int N,
    int relu_out, int relu_a)
{
    __shared__ float As[2][TK][TM + PADA];
    __shared__ float Bs[2][TK][TN + PADB];
    int tid = threadIdx.x;
    int m0 = blockIdx.y * TM;
    int n0 = blockIdx.x * TN;
    int tx = tid & 7;
    int ty = tid >> 3;
    int lr = tid >> 2;
    int lc = (tid & 3) * 4;

    ull acc[8][4];
    #pragma unroll
    for (int i = 0; i < 8; i++)
        #pragma unroll
        for (int j = 0; j < 4; j++) acc[i][j] = 0ULL;

    float4 ra[4], rb[2];
    int iters = (K1 + K2) / TK;

    auto LOAD = [&](int t) {
        int kv = t * TK;
        const float* A; const float* W; int lda, kk, wk;
        if (kv < K1) { A = A1; W = Wa; lda = lda1; kk = kv; wk = K1; }
        else         { A = A2; W = Wb; lda = lda2; kk = kv - K1; wk = K2; }
        #pragma unroll
        for (int p = 0; p < 4; p++) {
            int gr = m0 + lr + p * 32; if (gr >= M) gr = M - 1;
            float4 v = *(const float4*)(A + (size_t)gr * lda + kk + lc);
            if (relu_a) {
                v.x = fmaxf(v.x, 0.f); v.y = fmaxf(v.y, 0.f);
                v.z = fmaxf(v.z, 0.f); v.w = fmaxf(v.w, 0.f);
            }
            ra[p] = v;
        }
        #pragma unroll
        for (int p = 0; p < 2; p++) {
            int nn = n0 + lr + p * 32;
            rb[p] = *(const float4*)(W + (size_t)nn * wk + kk + lc);
        }
    };
    auto STORE = [&](int buf) {
        #pragma unroll
        for (int p = 0; p < 4; p++) {
            int r = lr + p * 32;
            As[buf][lc + 0][r] = ra[p].x; As[buf][lc + 1][r] = ra[p].y;
            As[buf][lc + 2][r] = ra[p].z; As[buf][lc + 3][r] = ra[p].w;
        }
        #pragma unroll
        for (int p = 0; p < 2; p++) {
            int r = lr + p * 32;
            Bs[buf][lc + 0][r] = rb[p].x; Bs[buf][lc + 1][r] = rb[p].y;
            Bs[buf][lc + 2][r] = rb[p].z; Bs[buf][lc + 3][r] = rb[p].w;
        }
    };

    LOAD(0);
    STORE(0);
    __syncthreads();

    #pragma unroll 1
    for (int t = 0; t < iters; t++) {
        if (t + 1 < iters) LOAD(t + 1);
        int cur = t & 1;
        #pragma unroll
        for (int kk = 0; kk < TK; kk++) {
            float4 b0 = *(const float4*)&Bs[cur][kk][tx * 8];
            float4 b1 = *(const float4*)&Bs[cur][kk][tx * 8 + 4];
            float4 a0 = *(const float4*)&As[cur][kk][ty * 8];
            float4 a1 = *(const float4*)&As[cur][kk][ty * 8 + 4];
            ull bp0 = pk(b0.x, b0.y), bp1 = pk(b0.z, b0.w);
            ull bp2 = pk(b1.x, b1.y), bp3 = pk(b1.z, b1.w);
            float av[8] = {a0.x, a0.y, a0.z, a0.w, a1.x, a1.y, a1.z, a1.w};
            #pragma unroll
            for (int i = 0; i < 8; i++) {
                ull ad = pk(av[i], av[i]);
                ffma2(acc[i][0], ad, bp0);
                ffma2(acc[i][1], ad, bp1);
                ffma2(acc[i][2], ad, bp2);
                ffma2(acc[i][3], ad, bp3);
            }
        }
        if (t + 1 < iters) {
            STORE((t + 1) & 1);
            __syncthreads();
        }
    }

    float4 bv0 = *(const float4*)(bias + n0 + tx * 8);
    float4 bv1 = *(const float4*)(bias + n0 + tx * 8 + 4);
    float bb[8] = {bv0.x, bv0.y, bv0.z, bv0.w, bv1.x, bv1.y, bv1.z, bv1.w};
    #pragma unroll
    for (int i = 0; i < 8; i++) {
        int gr = m0 + ty * 8 + i;
        if (gr < M) {
            float o[8];
            upk(o[0], o[1], acc[i][0]);
            upk(o[2], o[3], acc[i][1]);
            upk(o[4], o[5], acc[i][2]);
            upk(o[6], o[7], acc[i][3]);
            #pragma unroll
            for (int j = 0; j < 8; j++) {
                o[j] += bb[j];
                if (relu_out) o[j] = fmaxf(o[j], 0.f);
            }
            float* cp = C + (size_t)gr * N + n0 + tx * 8;
            *(float4*)cp       = make_float4(o[0], o[1], o[2], o[3]);
            *(float4*)(cp + 4) = make_float4(o[4], o[5], o[6], o[7]);
        }
    }
}

// ---------------- log_softmax over 128 cols, warp per row ----------------
__global__ void logsoftmax_kernel(const float* __restrict__ logits,
                                  float* __restrict__ out, int n) {
    int w = (blockIdx.x * blockDim.x + threadIdx.x) >> 5;
    int lane = threadIdx.x & 31;
    if (w >= n) return;
    float4 v = ((const float4*)(logits + (size_t)w * F_OUT))[lane];
    float m = fmaxf(fmaxf(v.x, v.y), fmaxf(v.z, v.w));
    #pragma unroll
    for (int o = 16; o > 0; o >>= 1) m = fmaxf(m, __shfl_xor_sync(0xFFFFFFFFu, m, o));
    float s = expf(v.x - m) + expf(v.y - m) + expf(v.z - m) + expf(v.w - m);
    #pragma unroll
    for (int o = 16; o > 0; o >>= 1) s += __shfl_xor_sync(0xFFFFFFFFu, s, o);
    float l = m + logf(s);
    float4 o4 = make_float4(v.x - l, v.y - l, v.z - l, v.w - l);
    ((float4*)(out + (size_t)w * F_OUT))[lane] = o4;
}

// ---------------- launch ----------------
extern "C" void kernel_launch(void* const* d_in, const int* in_sizes, int n_in,
                              void* d_out, int out_size) {
    const float* x   = (const float*)d_in[0];
    const int*   ei1 = (const int*)d_in[1];
    const int*   ei2 = (const int*)d_in[2];
    const float* Wl1 = (const float*)d_in[3];
    const float* bl1 = (const float*)d_in[4];
    const float* Wr1 = (const float*)d_in[5];
    const float* Wl2 = (const float*)d_in[6];
    const float* bl2 = (const float*)d_in[7];
    const float* Wr2 = (const float*)d_in[8];
    const float* W1  = (const float*)d_in[9];
    const float* b1  = (const float*)d_in[10];
    const float* W2  = (const float*)d_in[11];
    const float* b2  = (const float*)d_in[12];

    float* out = (float*)d_out;
    float* out_ls  = out;                           // [10000,128]
    float* out_emb = out + (size_t)N_TGT2 * F_OUT;  // [10000,192]

    int *deg1, *off1, *pos1, *idx1, *deg2, *off2, *pos2, *idx2, *bsum1, *bsum2;
    float *h1, *agg2, *h2, *logits;
    __nv_bfloat16 *ahi, *alo, *whi, *wlo;
    cudaGetSymbolAddress((void**)&deg1, g_deg1);
    cudaGetSymbolAddress((void**)&off1, g_off1);
    cudaGetSymbolAddress((void**)&pos1, g_pos1);
    cudaGetSymbolAddress((void**)&idx1, g_idx1);
    cudaGetSymbolAddress((void**)&deg2, g_deg2);
    cudaGetSymbolAddress((void**)&off2, g_off2);
    cudaGetSymbolAddress((void**)&pos2, g_pos2);
    cudaGetSymbolAddress((void**)&idx2, g_idx2);
    cudaGetSymbolAddress((void**)&bsum1, g_bsum1);
    cudaGetSymbolAddress((void**)&bsum2, g_bsum2);
    cudaGetSymbolAddress((void**)&h1, g_h1);
    cudaGetSymbolAddress((void**)&agg2, g_agg2);
    cudaGetSymbolAddress((void**)&h2, g_h2);
    cudaGetSymbolAddress((void**)&logits, g_logits);
    cudaGetSymbolAddress((void**)&ahi, g_ahi);
    cudaGetSymbolAddress((void**)&alo, g_alo);
    cudaGetSymbolAddress((void**)&whi, g_whi);
    cudaGetSymbolAddress((void**)&wlo, g_wlo);

    cudaFuncSetAttribute(mmagemm_kernel, cudaFuncAttributeMaxDynamicSharedMemorySize, MMA_SMEM);

    const int* tgt1 = ei1 + E1;
    const int* tgt2 = ei2 + E2;

    int nb1 = (N_TGT1 + 511) / 512;
    int nb2 = (N_TGT2 + 511) / 512;

    // CSR build
    zero_deg_kernel<<<(N_TGT1 + 255) / 256, 256>>>();
    hist_kernel<<<(E1 + 255) / 256, 256>>>(tgt1, E1, deg1);
    hist_kernel<<<(E2 + 255) / 256, 256>>>(tgt2, E2, deg2);
    scan_block_kernel<<<nb1, 512>>>(deg1, N_TGT1, off1, pos1, bsum1);
    scan_block_kernel<<<nb2, 512>>>(deg2, N_TGT2, off2, pos2, bsum2);
    scan_bsum_kernel<<<1, 128>>>(bsum1, nb1, off1);
    scan_bsum_kernel<<<1, 128>>>(bsum2, nb2, off2);
    scan_add_kernel<<<nb1, 512>>>(N_TGT1, off1, pos1, bsum1);
    scan_add_kernel<<<nb2, 512>>>(N_TGT2, off2, pos2, bsum2);
    fill_kernel<<<(E1 + 255) / 256, 256>>>(ei1, tgt1, E1, pos1, idx1);
    fill_kernel<<<(E2 + 255) / 256, 256>>>(ei2, tgt2, E2, pos2, idx2);

    // bf16 split conversions for layer-1 GEMM operands
    {
        int n4 = N_TGT1 * (F_IN / 4);
        convert_split_kernel<<<(n4 + 255) / 256, 256>>>(x, F_IN, ahi, alo, 512, 256, N_TGT1, F_IN);
        int w4 = F_HID * (F_IN / 4);
        convert_split_kernel<<<(w4 + 255) / 256, 256>>>(Wl1, F_IN, whi, wlo, 512, 0, F_HID, F_IN);
        convert_split_kernel<<<(w4 + 255) / 256, 256>>>(Wr1, F_IN, whi, wlo, 512, 256, F_HID, F_IN);
    }

    // Layer 1: agg (split output) + mma.sync GEMM
    agg_split_kernel<<<(N_TGT1 * 32 + 255) / 256, 256>>>(x, off1, idx1, ahi, alo, 512, N_TGT1);
    mmagemm_kernel<<<(N_TGT1 + 127) / 128, 256, MMA_SMEM>>>(ahi, alo, whi, wlo, bl1, h1, N_TGT1, 1);

    // Layer 2: h2 = relu(agg2@Wl2^T + h1@Wr2^T + bl2)
    agg_kernel<<<(N_TGT2 * 32 + 255) / 256, 256>>>(h1, F_HID, off2, idx2, agg2, N_TGT2);
    {
        dim3 grid(F_HID / TN, (N_TGT2 + TM - 1) / TM);
        gemm_kernel<<<grid, 128>>>(agg2, F_HID, Wl2, F_HID,
                                   h1, F_HID, Wr2, F_HID,
                                   bl2, h2, N_TGT2, F_HID, 1, 0);
    }

    // embedding = h2@W1^T + b1 -> d_out embedding region
    {
        dim3 grid(F_HID / TN, (N_TGT2 + TM - 1) / TM);
        gemm_kernel<<<grid, 128>>>(h2, F_HID, W1, F_HID,
                                   (const float*)0, 0, (const float*)0, 0,
                                   b1, out_emb, N_TGT2, F_HID, 0, 0);
    }

    // logits = relu(embedding)@W2^T + b2
    {
        dim3 grid(F_OUT / TN, (N_TGT2 + TM - 1) / TM);
        gemm_kernel<<<grid, 128>>>(out_emb, F_HID, W2, F_HID,
                                   (const float*)0, 0, (const float*)0, 0,
                                   b2, logits, N_TGT2, F_OUT, 0, 1);
    }

    // log_softmax
    logsoftmax_kernel<<<(N_TGT2 * 32 + 255) / 256, 256>>>(logits, out_ls, N_TGT2);
}

// round 5
// speedup vs baseline: 1.5180x; 1.0798x over previous
#include <cuda_runtime.h>
#include <cuda_bf16.h>
#include <math.h>
#include <stdint.h>

#define N_SRC1 200000
#define N_TGT1 50000
#define N_TGT2 10000
#define E1 1000000
#define E2 300000
#define F_IN 256
#define F_HID 192
#define F_OUT 128

// ---------------- scratch (device globals; allocation is forbidden) ----------------
__device__ int g_deg1[N_TGT1];
__device__ int g_off1[N_TGT1 + 1];
__device__ int g_pos1[N_TGT1];
__device__ int g_idx1[E1];

__device__ int g_deg2[N_TGT2];
__device__ int g_off2[N_TGT2 + 1];
__device__ int g_pos2[N_TGT2];
__device__ int g_idx2[E2];

__device__ int g_bsum1[256];
__device__ int g_bsum2[256];

// Layer-1 GEMM A/W: A = [agg1 | x[:50000]], K=512
__device__ __nv_bfloat16 g_ahi[(size_t)N_TGT1 * 512];
__device__ __nv_bfloat16 g_alo[(size_t)N_TGT1 * 512];
__device__ __nv_bfloat16 g_whi[(size_t)F_HID * 512];
__device__ __nv_bfloat16 g_wlo[(size_t)F_HID * 512];

// Layer-2 A: [agg2 | h1[:10000]], K=384 ; W2cat = [Wl2 | Wr2], [192,384]
__device__ __nv_bfloat16 g_a2hi[(size_t)N_TGT2 * 384];
__device__ __nv_bfloat16 g_a2lo[(size_t)N_TGT2 * 384];
__device__ __nv_bfloat16 g_w2hi[(size_t)F_HID * 384];
__device__ __nv_bfloat16 g_w2lo[(size_t)F_HID * 384];

// Layer-3 A: h2 [10000,192] ; W1 [192,192]
__device__ __nv_bfloat16 g_a3hi[(size_t)N_TGT2 * 192];
__device__ __nv_bfloat16 g_a3lo[(size_t)N_TGT2 * 192];
__device__ __nv_bfloat16 g_w3hi[(size_t)F_HID * 192];
__device__ __nv_bfloat16 g_w3lo[(size_t)F_HID * 192];

// Layer-4 A: relu(emb) [10000,192] ; W2 [128,192]
__device__ __nv_bfloat16 g_a4hi[(size_t)N_TGT2 * 192];
__device__ __nv_bfloat16 g_a4lo[(size_t)N_TGT2 * 192];
__device__ __nv_bfloat16 g_w4hi[(size_t)F_OUT * 192];
__device__ __nv_bfloat16 g_w4lo[(size_t)F_OUT * 192];

__device__ float g_h1[(size_t)N_TGT1 * F_HID];
__device__ float g_logits[(size_t)N_TGT2 * F_OUT];

// ---------------- bf16 split helpers ----------------
__device__ __forceinline__ void split1(float a, __nv_bfloat16& h, __nv_bfloat16& l) {
    h = __float2bfloat16_rn(a);
    l = __float2bfloat16_rn(a - __bfloat162float(h));
}

// ---------------- small kernels ----------------
__global__ void zero_deg_kernel() {
    int i = blockIdx.x * blockDim.x + threadIdx.x;
    if (i < N_TGT1) g_deg1[i] = 0;
    if (i < N_TGT2) g_deg2[i] = 0;
}

__global__ void hist_kernel(const int* __restrict__ tgt, int n, int* __restrict__ deg) {
    int i = blockIdx.x * blockDim.x + threadIdx.x;
    if (i < n) atomicAdd(&deg[tgt[i]], 1);
}

__global__ void scan_block_kernel(const int* __restrict__ deg, int n,
                                  int* __restrict__ off, int* __restrict__ pos,
                                  int* __restrict__ bsum) {
    __shared__ int wsum[16];
    int tid = threadIdx.x, lane = tid & 31, wid = tid >> 5;
    int i = blockIdx.x * 512 + tid;
    int v = (i < n) ? deg[i] : 0;
    int sc = v;
    #pragma unroll
    for (int o = 1; o < 32; o <<= 1) {
        int t = __shfl_up_sync(0xFFFFFFFFu, sc, o);
        if (lane >= o) sc += t;
    }
    if (lane == 31) wsum[wid] = sc;
    __syncthreads();
    if (wid == 0) {
        int ws = (lane < 16) ? wsum[lane] : 0;
        #pragma unroll
        for (int o = 1; o < 16; o <<= 1) {
            int t = __shfl_up_sync(0xFFFFFFFFu, ws, o);
            if (lane >= o) ws += t;
        }
        if (lane < 16) wsum[lane] = ws;
    }
    __syncthreads();
    int incl = sc + (wid ? wsum[wid - 1] : 0);
    if (i < n) { off[i + 1] = incl; pos[i] = incl - v; }
    if (tid == 511) bsum[blockIdx.x] = incl;
}

__global__ void scan_bsum_kernel(int* __restrict__ bsum, int nb, int* __restrict__ off) {
    __shared__ int s[128];
    int tid = threadIdx.x;
    int v = (tid < nb) ? bsum[tid] : 0;
    s[tid] = v;
    __syncthreads();
    #pragma unroll
    for (int o = 1; o < 128; o <<= 1) {
        int t = (tid >= o) ? s[tid - o] : 0;
        __syncthreads();
        s[tid] += t;
        __syncthreads();
    }
    if (tid < nb) bsum[tid] = s[tid] - v;
    if (tid == 0) off[0] = 0;
}

__global__ void scan_add_kernel(int n, int* __restrict__ off, int* __restrict__ pos,
                                const int* __restrict__ bsum) {
    int i = blockIdx.x * 512 + threadIdx.x;
    if (i < n) {
        int a = bsum[blockIdx.x];
        off[i + 1] += a;
        pos[i] += a;
    }
}

__global__ void fill_kernel(const int* __restrict__ src, const int* __restrict__ tgt,
                            int n, int* __restrict__ pos, int* __restrict__ idx) {
    int i = blockIdx.x * blockDim.x + threadIdx.x;
    if (i < n) {
        int p = atomicAdd(&pos[tgt[i]], 1);
        idx[p] = src[i];
    }
}

// ---------------- fp32 -> bf16 hi/lo split convert ----------------
__global__ void convert_split_kernel(const float* __restrict__ in, int in_lda,
                                     __nv_bfloat16* __restrict__ hi,
                                     __nv_bfloat16* __restrict__ lo,
                                     int out_lda, int out_col0,
                                     int rows, int cols) {
    int i = blockIdx.x * blockDim.x + threadIdx.x;
    int c4n = cols >> 2;
    if (i >= rows * c4n) return;
    int r = i / c4n, c = (i % c4n) << 2;
    float4 v = *(const float4*)(in + (size_t)r * in_lda + c);
    __nv_bfloat16 h0, h1, h2, h3, l0, l1, l2, l3;
    split1(v.x, h0, l0); split1(v.y, h1, l1);
    split1(v.z, h2, l2); split1(v.w, h3, l3);
    size_t o = (size_t)r * out_lda + out_col0 + c;
    *(__nv_bfloat162*)(hi + o)     = __nv_bfloat162(h0, h1);
    *(__nv_bfloat162*)(hi + o + 2) = __nv_bfloat162(h2, h3);
    *(__nv_bfloat162*)(lo + o)     = __nv_bfloat162(l0, l1);
    *(__nv_bfloat162*)(lo + o + 2) = __nv_bfloat162(l2, l3);
}

// ------- warp-per-target segment mean, 2-edge unrolled, bf16 split out -------
// F must be multiple of 128; lane covers float4 slots [lane] and [lane+32] (2nd if F==256... F/4>32)
__global__ void agg_split_kernel(const float* __restrict__ feat, int F,
                                 const int* __restrict__ off, const int* __restrict__ idx,
                                 __nv_bfloat16* __restrict__ hi,
                                 __nv_bfloat16* __restrict__ lo,
                                 int out_lda, int out_col0, int n_tgt) {
    int w = (blockIdx.x * blockDim.x + threadIdx.x) >> 5;
    int lane = threadIdx.x & 31;
    if (w >= n_tgt) return;
    int beg = off[w], end = off[w + 1];
    int F4 = F >> 2;
    bool two = (lane + 32) < F4;
    float4 a0 = make_float4(0.f, 0.f, 0.f, 0.f);
    float4 a1 = make_float4(0.f, 0.f, 0.f, 0.f);
    int e = beg;
    for (; e + 2 <= end; e += 2) {
        int i0 = idx[e], i1 = idx[e + 1];
        const float4* r0 = (const float4*)(feat + (size_t)i0 * F);
        const float4* r1 = (const float4*)(feat + (size_t)i1 * F);
        float4 v0 = __ldg(&r0[lane]);
        float4 v1 = __ldg(&r1[lane]);
        float4 u0, u1;
        if (two) { u0 = __ldg(&r0[lane + 32]); u1 = __ldg(&r1[lane + 32]); }
        a0.x += v0.x + v1.x; a0.y += v0.y + v1.y;
        a0.z += v0.z + v1.z; a0.w += v0.w + v1.w;
        if (two) {
            a1.x += u0.x + u1.x; a1.y += u0.y + u1.y;
            a1.z += u0.z + u1.z; a1.w += u0.w + u1.w;
        }
    }
    if (e < end) {
        const float4* r = (const float4*)(feat + (size_t)idx[e] * F);
        float4 v = __ldg(&r[lane]);
        a0.x += v.x; a0.y += v.y; a0.z += v.z; a0.w += v.w;
        if (two) {
            float4 u = __ldg(&r[lane + 32]);
            a1.x += u.x; a1.y += u.y; a1.z += u.z; a1.w += u.w;
        }
    }
    int c = end - beg;
    float s = 1.0f / (float)(c > 1 ? c : 1);
    a0.x *= s; a0.y *= s; a0.z *= s; a0.w *= s;
    __nv_bfloat16 h[4], l[4];
    split1(a0.x, h[0], l[0]); split1(a0.y, h[1], l[1]);
    split1(a0.z, h[2], l[2]); split1(a0.w, h[3], l[3]);
    size_t o0 = (size_t)w * out_lda + out_col0 + lane * 4;
    *(__nv_bfloat162*)(hi + o0)     = __nv_bfloat162(h[0], h[1]);
    *(__nv_bfloat162*)(hi + o0 + 2) = __nv_bfloat162(h[2], h[3]);
    *(__nv_bfloat162*)(lo + o0)     = __nv_bfloat162(l[0], l[1]);
    *(__nv_bfloat162*)(lo + o0 + 2) = __nv_bfloat162(l[2], l[3]);
    if (two) {
        a1.x *= s; a1.y *= s; a1.z *= s; a1.w *= s;
        split1(a1.x, h[0], l[0]); split1(a1.y, h[1], l[1]);
        split1(a1.z, h[2], l[2]); split1(a1.w, h[3], l[3]);
        size_t o1 = (size_t)w * out_lda + out_col0 + (lane + 32) * 4;
        *(__nv_bfloat162*)(hi + o1)     = __nv_bfloat162(h[0], h[1]);
        *(__nv_bfloat162*)(hi + o1 + 2) = __nv_bfloat162(h[2], h[3]);
        *(__nv_bfloat162*)(lo + o1)     = __nv_bfloat162(l[0], l[1]);
        *(__nv_bfloat162*)(lo + o1 + 2) = __nv_bfloat162(l[2], l[3]);
    }
}

// ================= mma.sync bf16 split GEMM (template on block N width) =================
// C[M,NN] = A[M,K] @ W[NN,K]^T + bias ; 3-term hi/lo split.
// Block 128M x NN, 256 threads (8 warps: 4m x 2n). K chunks of 32, cp.async dbuf.
#define ROWB 80

__device__ __forceinline__ uint32_t smem_u32(const void* p) {
    uint32_t a;
    asm("{ .reg .u64 t; cvta.to.shared.u64 t, %1; cvt.u32.u64 %0, t; }" : "=r"(a) : "l"(p));
    return a;
}
__device__ __forceinline__ void cp16(uint32_t s, const void* g) {
    asm volatile("cp.async.cg.shared.global [%0], [%1], 16;" :: "r"(s), "l"(g));
}
__device__ __forceinline__ void cp_commit() { asm volatile("cp.async.commit_group;"); }
__device__ __forceinline__ void cp_wait1() { asm volatile("cp.async.wait_group 1;"); }
__device__ __forceinline__ void ldm4(uint32_t* r, uint32_t a) {
    asm volatile("ldmatrix.sync.aligned.m8n8.x4.shared.b16 {%0,%1,%2,%3}, [%4];"
                 : "=r"(r[0]), "=r"(r[1]), "=r"(r[2]), "=r"(r[3]) : "r"(a));
}
__device__ __forceinline__ void mma_bf16(float* c, const uint32_t* a, uint32_t b0, uint32_t b1) {
    asm volatile("mma.sync.aligned.m16n8k16.row.col.f32.bf16.bf16.f32 "
                 "{%0,%1,%2,%3},{%4,%5,%6,%7},{%8,%9},{%0,%1,%2,%3};"
                 : "+f"(c[0]), "+f"(c[1]), "+f"(c[2]), "+f"(c[3])
                 : "r"(a[0]), "r"(a[1]), "r"(a[2]), "r"(a[3]), "r"(b0), "r"(b1));
}

template <int NN>
__global__ __launch_bounds__(256) void mmagemm_kernel(
    const __nv_bfloat16* __restrict__ ahi, const __nv_bfloat16* __restrict__ alo,
    const __nv_bfloat16* __restrict__ whi, const __nv_bfloat16* __restrict__ wlo,
    const float* __restrict__ bias, int M, int K,
    float* __restrict__ Cf32, int relu_f32,
    __nv_bfloat16* __restrict__ shi, __nv_bfloat16* __restrict__ slo,
    int s_lda, int s_col0, int s_maxrow)
{
    constexpr int NJ = NN / 32;           // 16-col tiles per warp
    constexpr int NBI = NN / 64;          // B-load iterations
    constexpr int SAHI = 0;
    constexpr int SALO = 128 * ROWB;
    constexpr int SBHI = 256 * ROWB;
    constexpr int SBLO = (256 + NN) * ROWB;
    constexpr int BUF = (256 + 2 * NN) * ROWB;

    extern __shared__ char sm[];
    uint32_t smb = smem_u32(sm);
    int tid = threadIdx.x;
    int w = tid >> 5, lane = tid & 31;
    int m0 = blockIdx.x * 128;
    int wm = (w >> 1) * 32;
    int wn = (w & 1) * (NN / 2);

    float acc[2][2 * NJ][4];
    #pragma unroll
    for (int i = 0; i < 2; i++)
        #pragma unroll
        for (int j = 0; j < 2 * NJ; j++)
            #pragma unroll
            for (int k = 0; k < 4; k++) acc[i][j][k] = 0.f;

    int arow = tid >> 2;
    int aseg = (tid & 3) * 16;
    int asegk = (tid & 3) * 8;
    int chunks = K >> 5;

    auto load_chunk = [&](int c) {
        int k0 = c * 32;
        uint32_t base = smb + (c & 1) * BUF;
        #pragma unroll
        for (int i = 0; i < 2; i++) {
            int row = arow + i * 64;
            int gr = m0 + row; if (gr >= M) gr = M - 1;
            size_t go = (size_t)gr * K + k0 + asegk;
            uint32_t so = row * ROWB + aseg;
            cp16(base + SAHI + so, ahi + go);
            cp16(base + SALO + so, alo + go);
        }
        #pragma unroll
        for (int i = 0; i < NBI; i++) {
            int row = arow + i * 64;
            size_t go = (size_t)row * K + k0 + asegk;
            uint32_t so = row * ROWB + aseg;
            cp16(base + SBHI + so, whi + go);
            cp16(base + SBLO + so, wlo + go);
        }
    };

    int grp = lane >> 3, lr = lane & 7;
    int a_row_off = lr + (grp & 1) * 8;
    int a_k_off = (grp >> 1) * 8;
    int b_row_off = (grp & 2) * 4 + lr;
    int b_k_off = (grp & 1) * 8;

    load_chunk(0);
    cp_commit();

    #pragma unroll 1
    for (int c = 0; c < chunks; c++) {
        if (c + 1 < chunks) load_chunk(c + 1);
        cp_commit();
        cp_wait1();
        __syncthreads();

        uint32_t base = smb + (c & 1) * BUF;
        #pragma unroll
        for (int s = 0; s < 2; s++) {
            uint32_t ah[2][4], al[2][4];
            #pragma unroll
            for (int mt = 0; mt < 2; mt++) {
                uint32_t ra = (wm + mt * 16 + a_row_off) * ROWB + (s * 16 + a_k_off) * 2;
                ldm4(ah[mt], base + SAHI + ra);
                ldm4(al[mt], base + SALO + ra);
            }
            #pragma unroll
            for (int j = 0; j < NJ; j++) {
                uint32_t rb = (wn + j * 16 + b_row_off) * ROWB + (s * 16 + b_k_off) * 2;
                uint32_t bh[4], bl[4];
                ldm4(bh, base + SBHI + rb);
                ldm4(bl, base + SBLO + rb);
                #pragma unroll
                for (int mt = 0; mt < 2; mt++) {
                    mma_bf16(acc[mt][2 * j],     ah[mt], bh[0], bh[1]);
                    mma_bf16(acc[mt][2 * j],     ah[mt], bl[0], bl[1]);
                    mma_bf16(acc[mt][2 * j],     al[mt], bh[0], bh[1]);
                    mma_bf16(acc[mt][2 * j + 1], ah[mt], bh[2], bh[3]);
                    mma_bf16(acc[mt][2 * j + 1], ah[mt], bl[2], bl[3]);
                    mma_bf16(acc[mt][2 * j + 1], al[mt], bh[2], bh[3]);
                }
            }
        }
        __syncthreads();
    }

    // epilogue: optional fp32 out + optional relu'd bf16-split out
    int g = lane >> 2, t = lane & 3;
    #pragma unroll
    for (int mt = 0; mt < 2; mt++) {
        int r0 = m0 + wm + mt * 16 + g;
        #pragma unroll
        for (int j = 0; j < 2 * NJ; j++) {
            int col = wn + j * 8 + 2 * t;
            float2 bv = *(const float2*)(bias + col);
            float o0 = acc[mt][j][0] + bv.x, o1 = acc[mt][j][1] + bv.y;
            float o2 = acc[mt][j][2] + bv.x, o3 = acc[mt][j][3] + bv.y;
            if (Cf32) {
                float p0 = o0, p1 = o1, p2 = o2, p3 = o3;
                if (relu_f32) {
                    p0 = fmaxf(p0, 0.f); p1 = fmaxf(p1, 0.f);
                    p2 = fmaxf(p2, 0.f); p3 = fmaxf(p3, 0.f);
                }
                if (r0 < M)     *(float2*)(Cf32 + (size_t)r0 * NN + col)       = make_float2(p0, p1);
                if (r0 + 8 < M) *(float2*)(Cf32 + (size_t)(r0 + 8) * NN + col) = make_float2(p2, p3);
            }
            if (shi) {
                o0 = fmaxf(o0, 0.f); o1 = fmaxf(o1, 0.f);
                o2 = fmaxf(o2, 0.f); o3 = fmaxf(o3, 0.f);
                __nv_bfloat16 h0, h1, h2, h3, l0, l1, l2, l3;
                split1(o0, h0, l0); split1(o1, h1, l1);
                split1(o2, h2, l2); split1(o3, h3, l3);
                if (r0 < s_maxrow) {
                    size_t o = (size_t)r0 * s_lda + s_col0 + col;
                    *(__nv_bfloat162*)(shi + o) = __nv_bfloat162(h0, h1);
                    *(__nv_bfloat162*)(slo + o) = __nv_bfloat162(l0, l1);
                }
                if (r0 + 8 < s_maxrow) {
                    size_t o = (size_t)(r0 + 8) * s_lda + s_col0 + col;
                    *(__nv_bfloat162*)(shi + o) = __nv_bfloat162(h2, h3);
                    *(__nv_bfloat162*)(slo + o) = __nv_bfloat162(l2, l3);
                }
            }
        }
    }
}

// ---------------- log_softmax over 128 cols, warp per row ----------------
__global__ void logsoftmax_kernel(const float* __restrict__ logits,
                                  float* __restrict__ out, int n) {
    int w = (blockIdx.x * blockDim.x + threadIdx.x) >> 5;
    int lane = threadIdx.x & 31;
    if (w >= n) return;
    float4 v = ((const float4*)(logits + (size_t)w * F_OUT))[lane];
    float m = fmaxf(fmaxf(v.x, v.y), fmaxf(v.z, v.w));
    #pragma unroll
    for (int o = 16; o > 0; o >>= 1) m = fmaxf(m, __shfl_xor_sync(0xFFFFFFFFu, m, o));
    float s = expf(v.x - m) + expf(v.y - m) + expf(v.z - m) + expf(v.w - m);
    #pragma unroll
    for (int o = 16; o > 0; o >>= 1) s += __shfl_xor_sync(0xFFFFFFFFu, s, o);
    float l = m + logf(s);
    float4 o4 = make_float4(v.x - l, v.y - l, v.z - l, v.w - l);
    ((float4*)(out + (size_t)w * F_OUT))[lane] = o4;
}

// ---------------- launch ----------------
extern "C" void kernel_launch(void* const* d_in, const int* in_sizes, int n_in,
                              void* d_out, int out_size) {
    const float* x   = (const float*)d_in[0];
    const int*   ei1 = (const int*)d_in[1];
    const int*   ei2 = (const int*)d_in[2];
    const float* Wl1 = (const float*)d_in[3];
    const float* bl1 = (const float*)d_in[4];
    const float* Wr1 = (const float*)d_in[5];
    const float* Wl2 = (const float*)d_in[6];
    const float* bl2 = (const float*)d_in[7];
    const float* Wr2 = (const float*)d_in[8];
    const float* W1  = (const float*)d_in[9];
    const float* b1  = (const float*)d_in[10];
    const float* W2  = (const float*)d_in[11];
    const float* b2  = (const float*)d_in[12];

    float* out = (float*)d_out;
    float* out_ls  = out;                           // [10000,128]
    float* out_emb = out + (size_t)N_TGT2 * F_OUT;  // [10000,192]

    int *deg1, *off1, *pos1, *idx1, *deg2, *off2, *pos2, *idx2, *bsum1, *bsum2;
    float *h1, *logits;
    __nv_bfloat16 *ahi, *alo, *whi, *wlo;
    __nv_bfloat16 *a2hi, *a2lo, *w2hi, *w2lo;
    __nv_bfloat16 *a3hi, *a3lo, *w3hi, *w3lo;
    __nv_bfloat16 *a4hi, *a4lo, *w4hi, *w4lo;
    cudaGetSymbolAddress((void**)&deg1, g_deg1);
    cudaGetSymbolAddress((void**)&off1, g_off1);
    cudaGetSymbolAddress((void**)&pos1, g_pos1);
    cudaGetSymbolAddress((void**)&idx1, g_idx1);
    cudaGetSymbolAddress((void**)&deg2, g_deg2);
    cudaGetSymbolAddress((void**)&off2, g_off2);
    cudaGetSymbolAddress((void**)&pos2, g_pos2);
    cudaGetSymbolAddress((void**)&idx2, g_idx2);
    cudaGetSymbolAddress((void**)&bsum1, g_bsum1);
    cudaGetSymbolAddress((void**)&bsum2, g_bsum2);
    cudaGetSymbolAddress((void**)&h1, g_h1);
    cudaGetSymbolAddress((void**)&logits, g_logits);
    cudaGetSymbolAddress((void**)&ahi, g_ahi);
    cudaGetSymbolAddress((void**)&alo, g_alo);
    cudaGetSymbolAddress((void**)&whi, g_whi);
    cudaGetSymbolAddress((void**)&wlo, g_wlo);
    cudaGetSymbolAddress((void**)&a2hi, g_a2hi);
    cudaGetSymbolAddress((void**)&a2lo, g_a2lo);
    cudaGetSymbolAddress((void**)&w2hi, g_w2hi);
    cudaGetSymbolAddress((void**)&w2lo, g_w2lo);
    cudaGetSymbolAddress((void**)&a3hi, g_a3hi);
    cudaGetSymbolAddress((void**)&a3lo, g_a3lo);
    cudaGetSymbolAddress((void**)&w3hi, g_w3hi);
    cudaGetSymbolAddress((void**)&w3lo, g_w3lo);
    cudaGetSymbolAddress((void**)&a4hi, g_a4hi);
    cudaGetSymbolAddress((void**)&a4lo, g_a4lo);
    cudaGetSymbolAddress((void**)&w4hi, g_w4hi);
    cudaGetSymbolAddress((void**)&w4lo, g_w4lo);

    const int SMEM192 = 2 * (256 + 2 * 192) * ROWB;  // 102400
    const int SMEM128 = 2 * (256 + 2 * 128) * ROWB;  // 81920
    cudaFuncSetAttribute(mmagemm_kernel<192>, cudaFuncAttributeMaxDynamicSharedMemorySize, SMEM192);
    cudaFuncSetAttribute(mmagemm_kernel<128>, cudaFuncAttributeMaxDynamicSharedMemorySize, SMEM128);

    const int* tgt1 = ei1 + E1;
    const int* tgt2 = ei2 + E2;

    int nb1 = (N_TGT1 + 511) / 512;
    int nb2 = (N_TGT2 + 511) / 512;

    // CSR build
    zero_deg_kernel<<<(N_TGT1 + 255) / 256, 256>>>();
    hist_kernel<<<(E1 + 255) / 256, 256>>>(tgt1, E1, deg1);
    hist_kernel<<<(E2 + 255) / 256, 256>>>(tgt2, E2, deg2);
    scan_block_kernel<<<nb1, 512>>>(deg1, N_TGT1, off1, pos1, bsum1);
    scan_block_kernel<<<nb2, 512>>>(deg2, N_TGT2, off2, pos2, bsum2);
    scan_bsum_kernel<<<1, 128>>>(bsum1, nb1, off1);
    scan_bsum_kernel<<<1, 128>>>(bsum2, nb2, off2);
    scan_add_kernel<<<nb1, 512>>>(N_TGT1, off1, pos1, bsum1);
    scan_add_kernel<<<nb2, 512>>>(N_TGT2, off2, pos2, bsum2);
    fill_kernel<<<(E1 + 255) / 256, 256>>>(ei1, tgt1, E1, pos1, idx1);
    fill_kernel<<<(E2 + 255) / 256, 256>>>(ei2, tgt2, E2, pos2, idx2);

    // weight + x[:50000] conversions
    {
        int n4 = N_TGT1 * (F_IN / 4);  // ONLY rows used as A-stream
        convert_split_kernel<<<(n4 + 255) / 256, 256>>>(x, F_IN, ahi, alo, 512, 256, N_TGT1, F_IN);
        int w4 = F_HID * (F_IN / 4);
        convert_split_kernel<<<(w4 + 255) / 256, 256>>>(Wl1, F_IN, whi, wlo, 512, 0, F_HID, F_IN);
        convert_split_kernel<<<(w4 + 255) / 256, 256>>>(Wr1, F_IN, whi, wlo, 512, 256, F_HID, F_IN);
        int h4 = F_HID * (F_HID / 4);
        convert_split_kernel<<<(h4 + 255) / 256, 256>>>(Wl2, F_HID, w2hi, w2lo, 384, 0, F_HID, F_HID);
        convert_split_kernel<<<(h4 + 255) / 256, 256>>>(Wr2, F_HID, w2hi, w2lo, 384, 192, F_HID, F_HID);
        convert_split_kernel<<<(h4 + 255) / 256, 256>>>(W1, F_HID, w3hi, w3lo, 192, 0, F_HID, F_HID);
        int o4 = F_OUT * (F_HID / 4);
        convert_split_kernel<<<(o4 + 255) / 256, 256>>>(W2, F_HID, w4hi, w4lo, 192, 0, F_OUT, F_HID);
    }

    // Layer 1: agg1 split -> ahi[:,0:256]; gemm -> h1 fp32 (relu) + h1 split for layer2 A-stream2
    agg_split_kernel<<<(N_TGT1 * 32 + 255) / 256, 256>>>(x, F_IN, off1, idx1, ahi, alo, 512, 0, N_TGT1);
    mmagemm_kernel<192><<<(N_TGT1 + 127) / 128, 256, SMEM192>>>(
        ahi, alo, whi, wlo, bl1, N_TGT1, 512,
        h1, 1,
        a2hi, a2lo, 384, 192, N_TGT2);

    // Layer 2: agg2 split -> a2[:,0:192]; gemm -> h2 split only
    agg_split_kernel<<<(N_TGT2 * 32 + 255) / 256, 256>>>(h1, F_HID, off2, idx2, a2hi, a2lo, 384, 0, N_TGT2);
    mmagemm_kernel<192><<<(N_TGT2 + 127) / 128, 256, SMEM192>>>(
        a2hi, a2lo, w2hi, w2lo, bl2, N_TGT2, 384,
        (float*)0, 0,
        a3hi, a3lo, 192, 0, N_TGT2);

    // Layer 3: embedding fp32 (no relu) -> d_out; relu(embedding) split -> a4
    mmagemm_kernel<192><<<(N_TGT2 + 127) / 128, 256, SMEM192>>>(
        a3hi, a3lo, w3hi, w3lo, b1, N_TGT2, 192,
        out_emb, 0,
        a4hi, a4lo, 192, 0, N_TGT2);

    // Layer 4: logits fp32
    mmagemm_kernel<128><<<(N_TGT2 + 127) / 128, 256, SMEM128>>>(
        a4hi, a4lo, w4hi, w4lo, b2, N_TGT2, 192,
        logits, 0,
        (__nv_bfloat16*)0, (__nv_bfloat16*)0, 0, 0, 0);

    // log_softmax
    logsoftmax_kernel<<<(N_TGT2 * 32 + 255) / 256, 256>>>(logits, out_ls, N_TGT2);
}

// round 6
// speedup vs baseline: 1.6055x; 1.0576x over previous
#include <cuda_runtime.h>
#include <cuda_bf16.h>
#include <math.h>
#include <stdint.h>

#define N_SRC1 200000
#define N_TGT1 50000
#define N_TGT2 10000
#define E1 1000000
#define E2 300000
#define F_IN 256
#define F_HID 192
#define F_OUT 128

// ---------------- scratch (device globals; allocation is forbidden) ----------------
__device__ int g_deg1[N_TGT1];
__device__ int g_off1[N_TGT1 + 1];
__device__ int g_pos1[N_TGT1];
__device__ int g_idx1[E1];

__device__ int g_deg2[N_TGT2];
__device__ int g_off2[N_TGT2 + 1];
__device__ int g_pos2[N_TGT2];
__device__ int g_idx2[E2];

__device__ int g_bsum1[256];
__device__ int g_bsum2[256];

// Layer-1 GEMM A/W: A = [agg1 | x[:50000]], K=512
__device__ __nv_bfloat16 g_ahi[(size_t)N_TGT1 * 512];
__device__ __nv_bfloat16 g_alo[(size_t)N_TGT1 * 512];
__device__ __nv_bfloat16 g_whi[(size_t)F_HID * 512];
__device__ __nv_bfloat16 g_wlo[(size_t)F_HID * 512];

// Layer-2 A: [agg2 | h1[:10000]], K=384 ; W2cat = [Wl2 | Wr2], [192,384]
__device__ __nv_bfloat16 g_a2hi[(size_t)N_TGT2 * 384];
__device__ __nv_bfloat16 g_a2lo[(size_t)N_TGT2 * 384];
__device__ __nv_bfloat16 g_w2hi[(size_t)F_HID * 384];
__device__ __nv_bfloat16 g_w2lo[(size_t)F_HID * 384];

// Layer-3 A: h2 [10000,192] ; W1 [192,192]
__device__ __nv_bfloat16 g_a3hi[(size_t)N_TGT2 * 192];
__device__ __nv_bfloat16 g_a3lo[(size_t)N_TGT2 * 192];
__device__ __nv_bfloat16 g_w3hi[(size_t)F_HID * 192];
__device__ __nv_bfloat16 g_w3lo[(size_t)F_HID * 192];

// Layer-4 A: relu(emb) [10000,192] ; W2 [128,192]
__device__ __nv_bfloat16 g_a4hi[(size_t)N_TGT2 * 192];
__device__ __nv_bfloat16 g_a4lo[(size_t)N_TGT2 * 192];
__device__ __nv_bfloat16 g_w4hi[(size_t)F_OUT * 192];
__device__ __nv_bfloat16 g_w4lo[(size_t)F_OUT * 192];

__device__ float g_h1[(size_t)N_TGT1 * F_HID];
__device__ float g_logits[(size_t)N_TGT2 * F_OUT];

// ---------------- bf16 split helpers ----------------
__device__ __forceinline__ void split1(float a, __nv_bfloat16& h, __nv_bfloat16& l) {
    h = __float2bfloat16_rn(a);
    l = __float2bfloat16_rn(a - __bfloat162float(h));
}

// ============ launch 1: convert x[:50000] split + zero deg arrays ============
__global__ void convx_zero_kernel(const float* __restrict__ x) {
    int i = blockIdx.x * blockDim.x + threadIdx.x;
    if (i < N_TGT1) g_deg1[i] = 0;
    if (i < N_TGT2) g_deg2[i] = 0;
    const int c4n = F_IN >> 2;  // 64
    if (i >= N_TGT1 * c4n) return;
    int r = i / c4n, c = (i % c4n) << 2;
    float4 v = *(const float4*)(x + (size_t)r * F_IN + c);
    __nv_bfloat16 h0, h1, h2, h3, l0, l1, l2, l3;
    split1(v.x, h0, l0); split1(v.y, h1, l1);
    split1(v.z, h2, l2); split1(v.w, h3, l3);
    size_t o = (size_t)r * 512 + 256 + c;
    *(__nv_bfloat162*)(g_ahi + o)     = __nv_bfloat162(h0, h1);
    *(__nv_bfloat162*)(g_ahi + o + 2) = __nv_bfloat162(h2, h3);
    *(__nv_bfloat162*)(g_alo + o)     = __nv_bfloat162(l0, l1);
    *(__nv_bfloat162*)(g_alo + o + 2) = __nv_bfloat162(l2, l3);
}

// ============ launch 2: histogram both edge lists ============
__global__ void hist_both_kernel(const int* __restrict__ ei1, const int* __restrict__ ei2) {
    int i = blockIdx.x * blockDim.x + threadIdx.x;
    if (i < E1) {
        atomicAdd(&g_deg1[ei1[E1 + i]], 1);
    } else if (i < E1 + E2) {
        int j = i - E1;
        atomicAdd(&g_deg2[ei2[E2 + j]], 1);
    }
}

// ============ launch 3: per-block scans for both lists ============
// blocks [0, nb1) -> list1 ; [nb1, nb1+nb2) -> list2
__global__ void scan_block_both_kernel(int nb1) {
    const int* deg; int* off; int* pos; int* bsum; int n; int b;
    if ((int)blockIdx.x < nb1) { deg = g_deg1; off = g_off1; pos = g_pos1; bsum = g_bsum1; n = N_TGT1; b = blockIdx.x; }
    else { deg = g_deg2; off = g_off2; pos = g_pos2; bsum = g_bsum2; n = N_TGT2; b = blockIdx.x - nb1; }
    __shared__ int wsum[16];
    int tid = threadIdx.x, lane = tid & 31, wid = tid >> 5;
    int i = b * 512 + tid;
    int v = (i < n) ? deg[i] : 0;
    int sc = v;
    #pragma unroll
    for (int o = 1; o < 32; o <<= 1) {
        int t = __shfl_up_sync(0xFFFFFFFFu, sc, o);
        if (lane >= o) sc += t;
    }
    if (lane == 31) wsum[wid] = sc;
    __syncthreads();
    if (wid == 0) {
        int ws = (lane < 16) ? wsum[lane] : 0;
        #pragma unroll
        for (int o = 1; o < 16; o <<= 1) {
            int t = __shfl_up_sync(0xFFFFFFFFu, ws, o);
            if (lane >= o) ws += t;
        }
        if (lane < 16) wsum[lane] = ws;
    }
    __syncthreads();
    int incl = sc + (wid ? wsum[wid - 1] : 0);
    if (i < n) { off[i + 1] = incl; pos[i] = incl - v; }  // local values
    if (tid == 511) bsum[b] = incl;
}

// ============ launch 4: exclusive scan of block sums, both lists ============
__global__ void scan_bsum_both_kernel(int nb1, int nb2) {
    int* bsum = blockIdx.x ? g_bsum2 : g_bsum1;
    int* off  = blockIdx.x ? g_off2  : g_off1;
    int nb    = blockIdx.x ? nb2 : nb1;
    __shared__ int s[128];
    int tid = threadIdx.x;
    int v = (tid < nb) ? bsum[tid] : 0;
    s[tid] = v;
    __syncthreads();
    #pragma unroll
    for (int o = 1; o < 128; o <<= 1) {
        int t = (tid >= o) ? s[tid - o] : 0;
        __syncthreads();
        s[tid] += t;
        __syncthreads();
    }
    if (tid < nb) bsum[tid] = s[tid] - v;  // exclusive block offsets
    if (tid == 0) off[0] = 0;
}

// ============ launch 5: fill CSR for both lists (adds block offset inline) ============
__global__ void fill_both_kernel(const int* __restrict__ ei1, const int* __restrict__ ei2) {
    int i = blockIdx.x * blockDim.x + threadIdx.x;
    if (i < E1) {
        int t = ei1[E1 + i];
        int p = atomicAdd(&g_pos1[t], 1) + g_bsum1[t >> 9];
        g_idx1[p] = ei1[i];
    } else if (i < E1 + E2) {
        int j = i - E1;
        int t = ei2[E2 + j];
        int p = atomicAdd(&g_pos2[t], 1) + g_bsum2[t >> 9];
        g_idx2[p] = ei2[j];
    }
}

__device__ __forceinline__ int seg_beg(const int* off, const int* bsum, int w) {
    return w ? off[w] + bsum[(w - 1) >> 9] : 0;
}
__device__ __forceinline__ int seg_end(const int* off, const int* bsum, int w) {
    return off[w + 1] + bsum[w >> 9];
}

// ============ launch 6: layer-1 segment mean, 2 warps per target, 4-edge unroll ============
__global__ void agg1_kernel(const float* __restrict__ feat) {
    int gw = (blockIdx.x * blockDim.x + threadIdx.x) >> 5;
    int lane = threadIdx.x & 31;
    if (gw >= N_TGT1 * 2) return;
    int w = gw >> 1, h = gw & 1;
    int slot = h * 32 + lane;                 // float4 slot 0..63
    int beg = seg_beg(g_off1, g_bsum1, w);
    int end = seg_end(g_off1, g_bsum1, w);
    float4 a = make_float4(0.f, 0.f, 0.f, 0.f);
    int e = beg;
    for (; e + 4 <= end; e += 4) {
        int i0 = g_idx1[e], i1 = g_idx1[e + 1], i2 = g_idx1[e + 2], i3 = g_idx1[e + 3];
        float4 v0 = __ldg((const float4*)(feat + (size_t)i0 * F_IN) + slot);
        float4 v1 = __ldg((const float4*)(feat + (size_t)i1 * F_IN) + slot);
        float4 v2 = __ldg((const float4*)(feat + (size_t)i2 * F_IN) + slot);
        float4 v3 = __ldg((const float4*)(feat + (size_t)i3 * F_IN) + slot);
        a.x += (v0.x + v1.x) + (v2.x + v3.x);
        a.y += (v0.y + v1.y) + (v2.y + v3.y);
        a.z += (v0.z + v1.z) + (v2.z + v3.z);
        a.w += (v0.w + v1.w) + (v2.w + v3.w);
    }
    for (; e < end; e++) {
        float4 v = __ldg((const float4*)(feat + (size_t)g_idx1[e] * F_IN) + slot);
        a.x += v.x; a.y += v.y; a.z += v.z; a.w += v.w;
    }
    int c = end - beg;
    float s = 1.0f / (float)(c > 1 ? c : 1);
    a.x *= s; a.y *= s; a.z *= s; a.w *= s;
    __nv_bfloat16 hh[4], ll[4];
    split1(a.x, hh[0], ll[0]); split1(a.y, hh[1], ll[1]);
    split1(a.z, hh[2], ll[2]); split1(a.w, hh[3], ll[3]);
    size_t o = (size_t)w * 512 + slot * 4;
    *(__nv_bfloat162*)(g_ahi + o)     = __nv_bfloat162(hh[0], hh[1]);
    *(__nv_bfloat162*)(g_ahi + o + 2) = __nv_bfloat162(hh[2], hh[3]);
    *(__nv_bfloat162*)(g_alo + o)     = __nv_bfloat162(ll[0], ll[1]);
    *(__nv_bfloat162*)(g_alo + o + 2) = __nv_bfloat162(ll[2], ll[3]);
}

// ============ launch 7: all weight converts fused ============
// quads: Wl1 12288 | Wr1 12288 | Wl2 9216 | Wr2 9216 | W1 9216 | W2 6144  (total 58368)
__global__ void convw_all_kernel(const float* __restrict__ Wl1, const float* __restrict__ Wr1,
                                 const float* __restrict__ Wl2, const float* __restrict__ Wr2,
                                 const float* __restrict__ W1, const float* __restrict__ W2) {
    int i = blockIdx.x * blockDim.x + threadIdx.x;
    const float* in; __nv_bfloat16* hi; __nv_bfloat16* lo;
    int q, c4n, lda, col0;
    if (i < 12288)      { in = Wl1; hi = g_whi;  lo = g_wlo;  q = i;          c4n = 64; lda = 512; col0 = 0; }
    else if (i < 24576) { in = Wr1; hi = g_whi;  lo = g_wlo;  q = i - 12288;  c4n = 64; lda = 512; col0 = 256; }
    else if (i < 33792) { in = Wl2; hi = g_w2hi; lo = g_w2lo; q = i - 24576;  c4n = 48; lda = 384; col0 = 0; }
    else if (i < 43008) { in = Wr2; hi = g_w2hi; lo = g_w2lo; q = i - 33792;  c4n = 48; lda = 384; col0 = 192; }
    else if (i < 52224) { in = W1;  hi = g_w3hi; lo = g_w3lo; q = i - 43008;  c4n = 48; lda = 192; col0 = 0; }
    else if (i < 58368) { in = W2;  hi = g_w4hi; lo = g_w4lo; q = i - 52224;  c4n = 48; lda = 192; col0 = 0; }
    else return;
    int r = q / c4n, c = (q % c4n) << 2;
    float4 v = *(const float4*)(in + (size_t)r * (c4n * 4) + c);
    __nv_bfloat16 h0, h1, h2, h3, l0, l1, l2, l3;
    split1(v.x, h0, l0); split1(v.y, h1, l1);
    split1(v.z, h2, l2); split1(v.w, h3, l3);
    size_t o = (size_t)r * lda + col0 + c;
    *(__nv_bfloat162*)(hi + o)     = __nv_bfloat162(h0, h1);
    *(__nv_bfloat162*)(hi + o + 2) = __nv_bfloat162(h2, h3);
    *(__nv_bfloat162*)(lo + o)     = __nv_bfloat162(l0, l1);
    *(__nv_bfloat162*)(lo + o + 2) = __nv_bfloat162(l2, l3);
}

// ============ layer-2 segment mean (F=192), warp/target, 4-edge unroll ============
__global__ void agg2_kernel(const float* __restrict__ feat) {
    int w = (blockIdx.x * blockDim.x + threadIdx.x) >> 5;
    int lane = threadIdx.x & 31;
    if (w >= N_TGT2) return;
    int beg = seg_beg(g_off2, g_bsum2, w);
    int end = seg_end(g_off2, g_bsum2, w);
    bool two = lane < 16;                       // slots: lane and lane+32 (48 total)
    float4 a0 = make_float4(0.f, 0.f, 0.f, 0.f);
    float4 a1 = make_float4(0.f, 0.f, 0.f, 0.f);
    int e = beg;
    for (; e + 2 <= end; e += 2) {
        int i0 = g_idx2[e], i1 = g_idx2[e + 1];
        const float4* r0 = (const float4*)(feat + (size_t)i0 * F_HID);
        const float4* r1 = (const float4*)(feat + (size_t)i1 * F_HID);
        float4 v0 = __ldg(r0 + lane);
        float4 v1 = __ldg(r1 + lane);
        if (two) {
            float4 u0 = __ldg(r0 + lane + 32);
            float4 u1 = __ldg(r1 + lane + 32);
            a1.x += u0.x + u1.x; a1.y += u0.y + u1.y;
            a1.z += u0.z + u1.z; a1.w += u0.w + u1.w;
        }
        a0.x += v0.x + v1.x; a0.y += v0.y + v1.y;
        a0.z += v0.z + v1.z; a0.w += v0.w + v1.w;
    }
    if (e < end) {
        const float4* r = (const float4*)(feat + (size_t)g_idx2[e] * F_HID);
        float4 v = __ldg(r + lane);
        a0.x += v.x; a0.y += v.y; a0.z += v.z; a0.w += v.w;
        if (two) {
            float4 u = __ldg(r + lane + 32);
            a1.x += u.x; a1.y += u.y; a1.z += u.z; a1.w += u.w;
        }
    }
    int c = end - beg;
    float s = 1.0f / (float)(c > 1 ? c : 1);
    a0.x *= s; a0.y *= s; a0.z *= s; a0.w *= s;
    __nv_bfloat16 h[4], l[4];
    split1(a0.x, h[0], l[0]); split1(a0.y, h[1], l[1]);
    split1(a0.z, h[2], l[2]); split1(a0.w, h[3], l[3]);
    size_t o0 = (size_t)w * 384 + lane * 4;
    *(__nv_bfloat162*)(g_a2hi + o0)     = __nv_bfloat162(h[0], h[1]);
    *(__nv_bfloat162*)(g_a2hi + o0 + 2) = __nv_bfloat162(h[2], h[3]);
    *(__nv_bfloat162*)(g_a2lo + o0)     = __nv_bfloat162(l[0], l[1]);
    *(__nv_bfloat162*)(g_a2lo + o0 + 2) = __nv_bfloat162(l[2], l[3]);
    if (two) {
        a1.x *= s; a1.y *= s; a1.z *= s; a1.w *= s;
        split1(a1.x, h[0], l[0]); split1(a1.y, h[1], l[1]);
        split1(a1.z, h[2], l[2]); split1(a1.w, h[3], l[3]);
        size_t o1 = (size_t)w * 384 + (lane + 32) * 4;
        *(__nv_bfloat162*)(g_a2hi + o1)     = __nv_bfloat162(h[0], h[1]);
        *(__nv_bfloat162*)(g_a2hi + o1 + 2) = __nv_bfloat162(h[2], h[3]);
        *(__nv_bfloat162*)(g_a2lo + o1)     = __nv_bfloat162(l[0], l[1]);
        *(__nv_bfloat162*)(g_a2lo + o1 + 2) = __nv_bfloat162(l[2], l[3]);
    }
}

// ================= mma.sync bf16 split GEMM (template on block N width) =================
#define ROWB 80

__device__ __forceinline__ uint32_t smem_u32(const void* p) {
    uint32_t a;
    asm("{ .reg .u64 t; cvta.to.shared.u64 t, %1; cvt.u32.u64 %0, t; }" : "=r"(a) : "l"(p));
    return a;
}
__device__ __forceinline__ void cp16(uint32_t s, const void* g) {
    asm volatile("cp.async.cg.shared.global [%0], [%1], 16;" :: "r"(s), "l"(g));
}
__device__ __forceinline__ void cp_commit() { asm volatile("cp.async.commit_group;"); }
__device__ __forceinline__ void cp_wait1() { asm volatile("cp.async.wait_group 1;"); }
__device__ __forceinline__ void ldm4(uint32_t* r, uint32_t a) {
    asm volatile("ldmatrix.sync.aligned.m8n8.x4.shared.b16 {%0,%1,%2,%3}, [%4];"
                 : "=r"(r[0]), "=r"(r[1]), "=r"(r[2]), "=r"(r[3]) : "r"(a));
}
__device__ __forceinline__ void mma_bf16(float* c, const uint32_t* a, uint32_t b0, uint32_t b1) {
    asm volatile("mma.sync.aligned.m16n8k16.row.col.f32.bf16.bf16.f32 "
                 "{%0,%1,%2,%3},{%4,%5,%6,%7},{%8,%9},{%0,%1,%2,%3};"
                 : "+f"(c[0]), "+f"(c[1]), "+f"(c[2]), "+f"(c[3])
                 : "r"(a[0]), "r"(a[1]), "r"(a[2]), "r"(a[3]), "r"(b0), "r"(b1));
}

template <int NN>
__global__ __launch_bounds__(256) void mmagemm_kernel(
    const __nv_bfloat16* __restrict__ ahi, const __nv_bfloat16* __restrict__ alo,
    const __nv_bfloat16* __restrict__ whi, const __nv_bfloat16* __restrict__ wlo,
    const float* __restrict__ bias, int M, int K,
    float* __restrict__ Cf32, int relu_f32,
    __nv_bfloat16* __restrict__ shi, __nv_bfloat16* __restrict__ slo,
    int s_lda, int s_col0, int s_maxrow)
{
    constexpr int NJ = NN / 32;
    constexpr int NBI = NN / 64;
    constexpr int SAHI = 0;
    constexpr int SALO = 128 * ROWB;
    constexpr int SBHI = 256 * ROWB;
    constexpr int SBLO = (256 + NN) * ROWB;
    constexpr int BUF = (256 + 2 * NN) * ROWB;

    extern __shared__ char sm[];
    uint32_t smb = smem_u32(sm);
    int tid = threadIdx.x;
    int w = tid >> 5, lane = tid & 31;
    int m0 = blockIdx.x * 128;
    int wm = (w >> 1) * 32;
    int wn = (w & 1) * (NN / 2);

    float acc[2][2 * NJ][4];
    #pragma unroll
    for (int i = 0; i < 2; i++)
        #pragma unroll
        for (int j = 0; j < 2 * NJ; j++)
            #pragma unroll
            for (int k = 0; k < 4; k++) acc[i][j][k] = 0.f;

    int arow = tid >> 2;
    int aseg = (tid & 3) * 16;
    int asegk = (tid & 3) * 8;
    int chunks = K >> 5;

    auto load_chunk = [&](int c) {
        int k0 = c * 32;
        uint32_t base = smb + (c & 1) * BUF;
        #pragma unroll
        for (int i = 0; i < 2; i++) {
            int row = arow + i * 64;
            int gr = m0 + row; if (gr >= M) gr = M - 1;
            size_t go = (size_t)gr * K + k0 + asegk;
            uint32_t so = row * ROWB + aseg;
            cp16(base + SAHI + so, ahi + go);
            cp16(base + SALO + so, alo + go);
        }
        #pragma unroll
        for (int i = 0; i < NBI; i++) {
            int row = arow + i * 64;
            size_t go = (size_t)row * K + k0 + asegk;
            uint32_t so = row * ROWB + aseg;
            cp16(base + SBHI + so, whi + go);
            cp16(base + SBLO + so, wlo + go);
        }
    };

    int grp = lane >> 3, lr = lane & 7;
    int a_row_off = lr + (grp & 1) * 8;
    int a_k_off = (grp >> 1) * 8;
    int b_row_off = (grp & 2) * 4 + lr;
    int b_k_off = (grp & 1) * 8;

    load_chunk(0);
    cp_commit();

    #pragma unroll 1
    for (int c = 0; c < chunks; c++) {
        if (c + 1 < chunks) load_chunk(c + 1);
        cp_commit();
        cp_wait1();
        __syncthreads();

        uint32_t base = smb + (c & 1) * BUF;
        #pragma unroll
        for (int s = 0; s < 2; s++) {
            uint32_t ah[2][4], al[2][4];
            #pragma unroll
            for (int mt = 0; mt < 2; mt++) {
                uint32_t ra = (wm + mt * 16 + a_row_off) * ROWB + (s * 16 + a_k_off) * 2;
                ldm4(ah[mt], base + SAHI + ra);
                ldm4(al[mt], base + SALO + ra);
            }
            #pragma unroll
            for (int j = 0; j < NJ; j++) {
                uint32_t rb = (wn + j * 16 + b_row_off) * ROWB + (s * 16 + b_k_off) * 2;
                uint32_t bh[4], bl[4];
                ldm4(bh, base + SBHI + rb);
                ldm4(bl, base + SBLO + rb);
                #pragma unroll
                for (int mt = 0; mt < 2; mt++) {
                    mma_bf16(acc[mt][2 * j],     ah[mt], bh[0], bh[1]);
                    mma_bf16(acc[mt][2 * j],     ah[mt], bl[0], bl[1]);
                    mma_bf16(acc[mt][2 * j],     al[mt], bh[0], bh[1]);
                    mma_bf16(acc[mt][2 * j + 1], ah[mt], bh[2], bh[3]);
                    mma_bf16(acc[mt][2 * j + 1], ah[mt], bl[2], bl[3]);
                    mma_bf16(acc[mt][2 * j + 1], al[mt], bh[2], bh[3]);
                }
            }
        }
        __syncthreads();
    }

    int g = lane >> 2, t = lane & 3;
    #pragma unroll
    for (int mt = 0; mt < 2; mt++) {
        int r0 = m0 + wm + mt * 16 + g;
        #pragma unroll
        for (int j = 0; j < 2 * NJ; j++) {
            int col = wn + j * 8 + 2 * t;
            float2 bv = *(const float2*)(bias + col);
            float o0 = acc[mt][j][0] + bv.x, o1 = acc[mt][j][1] + bv.y;
            float o2 = acc[mt][j][2] + bv.x, o3 = acc[mt][j][3] + bv.y;
            if (Cf32) {
                float p0 = o0, p1 = o1, p2 = o2, p3 = o3;
                if (relu_f32) {
                    p0 = fmaxf(p0, 0.f); p1 = fmaxf(p1, 0.f);
                    p2 = fmaxf(p2, 0.f); p3 = fmaxf(p3, 0.f);
                }
                if (r0 < M)     *(float2*)(Cf32 + (size_t)r0 * NN + col)       = make_float2(p0, p1);
                if (r0 + 8 < M) *(float2*)(Cf32 + (size_t)(r0 + 8) * NN + col) = make_float2(p2, p3);
            }
            if (shi) {
                o0 = fmaxf(o0, 0.f); o1 = fmaxf(o1, 0.f);
                o2 = fmaxf(o2, 0.f); o3 = fmaxf(o3, 0.f);
                __nv_bfloat16 h0, h1, h2, h3, l0, l1, l2, l3;
                split1(o0, h0, l0); split1(o1, h1, l1);
                split1(o2, h2, l2); split1(o3, h3, l3);
                if (r0 < s_maxrow) {
                    size_t o = (size_t)r0 * s_lda + s_col0 + col;
                    *(__nv_bfloat162*)(shi + o) = __nv_bfloat162(h0, h1);
                    *(__nv_bfloat162*)(slo + o) = __nv_bfloat162(l0, l1);
                }
                if (r0 + 8 < s_maxrow) {
                    size_t o = (size_t)(r0 + 8) * s_lda + s_col0 + col;
                    *(__nv_bfloat162*)(shi + o) = __nv_bfloat162(h2, h3);
                    *(__nv_bfloat162*)(slo + o) = __nv_bfloat162(l2, l3);
                }
            }
        }
    }
}

// ---------------- log_softmax over 128 cols, warp per row ----------------
__global__ void logsoftmax_kernel(const float* __restrict__ logits,
                                  float* __restrict__ out, int n) {
    int w = (blockIdx.x * blockDim.x + threadIdx.x) >> 5;
    int lane = threadIdx.x & 31;
    if (w >= n) return;
    float4 v = ((const float4*)(logits + (size_t)w * F_OUT))[lane];
    float m = fmaxf(fmaxf(v.x, v.y), fmaxf(v.z, v.w));
    #pragma unroll
    for (int o = 16; o > 0; o >>= 1) m = fmaxf(m, __shfl_xor_sync(0xFFFFFFFFu, m, o));
    float s = expf(v.x - m) + expf(v.y - m) + expf(v.z - m) + expf(v.w - m);
    #pragma unroll
    for (int o = 16; o > 0; o >>= 1) s += __shfl_xor_sync(0xFFFFFFFFu, s, o);
    float l = m + logf(s);
    float4 o4 = make_float4(v.x - l, v.y - l, v.z - l, v.w - l);
    ((float4*)(out + (size_t)w * F_OUT))[lane] = o4;
}

// ---------------- launch ----------------
extern "C" void kernel_launch(void* const* d_in, const int* in_sizes, int n_in,
                              void* d_out, int out_size) {
    const float* x   = (const float*)d_in[0];
    const int*   ei1 = (const int*)d_in[1];
    const int*   ei2 = (const int*)d_in[2];
    const float* Wl1 = (const float*)d_in[3];
    const float* bl1 = (const float*)d_in[4];
    const float* Wr1 = (const float*)d_in[5];
    const float* Wl2 = (const float*)d_in[6];
    const float* bl2 = (const float*)d_in[7];
    const float* Wr2 = (const float*)d_in[8];
    const float* W1  = (const float*)d_in[9];
    const float* b1  = (const float*)d_in[10];
    const float* W2  = (const float*)d_in[11];
    const float* b2  = (const float*)d_in[12];

    float* out = (float*)d_out;
    float* out_ls  = out;                           // [10000,128]
    float* out_emb = out + (size_t)N_TGT2 * F_OUT;  // [10000,192]

    float *h1, *logits;
    __nv_bfloat16 *ahi, *alo, *whi, *wlo;
    __nv_bfloat16 *a2hi, *a2lo, *w2hi, *w2lo;
    __nv_bfloat16 *a3hi, *a3lo, *w3hi, *w3lo;
    __nv_bfloat16 *a4hi, *a4lo, *w4hi, *w4lo;
    cudaGetSymbolAddress((void**)&h1, g_h1);
    cudaGetSymbolAddress((void**)&logits, g_logits);
    cudaGetSymbolAddress((void**)&ahi, g_ahi);
    cudaGetSymbolAddress((void**)&alo, g_alo);
    cudaGetSymbolAddress((void**)&whi, g_whi);
    cudaGetSymbolAddress((void**)&wlo, g_wlo);
    cudaGetSymbolAddress((void**)&a2hi, g_a2hi);
    cudaGetSymbolAddress((void**)&a2lo, g_a2lo);
    cudaGetSymbolAddress((void**)&w2hi, g_w2hi);
    cudaGetSymbolAddress((void**)&w2lo, g_w2lo);
    cudaGetSymbolAddress((void**)&a3hi, g_a3hi);
    cudaGetSymbolAddress((void**)&a3lo, g_a3lo);
    cudaGetSymbolAddress((void**)&w3hi, g_w3hi);
    cudaGetSymbolAddress((void**)&w3lo, g_w3lo);
    cudaGetSymbolAddress((void**)&a4hi, g_a4hi);
    cudaGetSymbolAddress((void**)&a4lo, g_a4lo);
    cudaGetSymbolAddress((void**)&w4hi, g_w4hi);
    cudaGetSymbolAddress((void**)&w4lo, g_w4lo);

    const int SMEM192 = 2 * (256 + 2 * 192) * ROWB;  // 102400
    const int SMEM128 = 2 * (256 + 2 * 128) * ROWB;  // 81920
    cudaFuncSetAttribute(mmagemm_kernel<192>, cudaFuncAttributeMaxDynamicSharedMemorySize, SMEM192);
    cudaFuncSetAttribute(mmagemm_kernel<128>, cudaFuncAttributeMaxDynamicSharedMemorySize, SMEM128);

    int nb1 = (N_TGT1 + 511) / 512;  // 98
    int nb2 = (N_TGT2 + 511) / 512;  // 20

    // 1: convert x[:50000] + zero deg
    {
        int n = N_TGT1 * (F_IN / 4);
        convx_zero_kernel<<<(n + 255) / 256, 256>>>(x);
    }
    // 2-5: CSR build (hist, block scan, bsum scan, fill)
    hist_both_kernel<<<(E1 + E2 + 255) / 256, 256>>>(ei1, ei2);
    scan_block_both_kernel<<<nb1 + nb2, 512>>>(nb1);
    scan_bsum_both_kernel<<<2, 128>>>(nb1, nb2);
    fill_both_kernel<<<(E1 + E2 + 255) / 256, 256>>>(ei1, ei2);

    // 6: layer-1 aggregation (PROFILED SLOT)
    agg1_kernel<<<(N_TGT1 * 2 * 32 + 255) / 256, 256>>>(x);

    // 7: all weight converts
    convw_all_kernel<<<(58368 + 255) / 256, 256>>>(Wl1, Wr1, Wl2, Wr2, W1, W2);

    // 8: layer-1 GEMM -> h1 fp32 (relu) + h1 split rows<10000 for layer-2 stream
    mmagemm_kernel<192><<<(N_TGT1 + 127) / 128, 256, SMEM192>>>(
        ahi, alo, whi, wlo, bl1, N_TGT1, 512,
        h1, 1,
        a2hi, a2lo, 384, 192, N_TGT2);

    // 9: layer-2 aggregation
    agg2_kernel<<<(N_TGT2 * 32 + 255) / 256, 256>>>(h1);

    // 10: layer-2 GEMM -> h2 split
    mmagemm_kernel<192><<<(N_TGT2 + 127) / 128, 256, SMEM192>>>(
        a2hi, a2lo, w2hi, w2lo, bl2, N_TGT2, 384,
        (float*)0, 0,
        a3hi, a3lo, 192, 0, N_TGT2);

    // 11: layer-3 GEMM -> embedding fp32 + relu(emb) split
    mmagemm_kernel<192><<<(N_TGT2 + 127) / 128, 256, SMEM192>>>(
        a3hi, a3lo, w3hi, w3lo, b1, N_TGT2, 192,
        out_emb, 0,
        a4hi, a4lo, 192, 0, N_TGT2);

    // 12: layer-4 GEMM -> logits
    mmagemm_kernel<128><<<(N_TGT2 + 127) / 128, 256, SMEM128>>>(
        a4hi, a4lo, w4hi, w4lo, b2, N_TGT2, 192,
        logits, 0,
        (__nv_bfloat16*)0, (__nv_bfloat16*)0, 0, 0, 0);

    // 13: log_softmax
    logsoftmax_kernel<<<(N_TGT2 * 32 + 255) / 256, 256>>>(logits, out_ls, N_TGT2);
}

// round 7
// speedup vs baseline: 1.6140x; 1.0053x over previous
#include <cuda_runtime.h>
#include <cuda_bf16.h>
#include <math.h>
#include <stdint.h>

#define N_SRC1 200000
#define N_TGT1 50000
#define N_TGT2 10000
#define E1 1000000
#define E2 300000
#define F_IN 256
#define F_HID 192
#define F_OUT 128

// ---------------- scratch (device globals; allocation is forbidden) ----------------
__device__ int g_deg1[N_TGT1];
__device__ int g_off1[N_TGT1 + 1];
__device__ int g_pos1[N_TGT1];
__device__ int g_idx1[E1];

__device__ int g_deg2[N_TGT2];
__device__ int g_off2[N_TGT2 + 1];
__device__ int g_pos2[N_TGT2];
__device__ int g_idx2[E2];

__device__ int g_bsum1[256];
__device__ int g_bsum2[256];
__device__ int g_ctr[2];

// Layer-1 GEMM A/W: A = [agg1 | x[:50000]], K=512
__device__ __nv_bfloat16 g_ahi[(size_t)N_TGT1 * 512];
__device__ __nv_bfloat16 g_alo[(size_t)N_TGT1 * 512];
__device__ __nv_bfloat16 g_whi[(size_t)F_HID * 512];
__device__ __nv_bfloat16 g_wlo[(size_t)F_HID * 512];

// Layer-2 A: [agg2 | h1[:10000]], K=384 ; W2cat = [Wl2 | Wr2]
__device__ __nv_bfloat16 g_a2hi[(size_t)N_TGT2 * 384];
__device__ __nv_bfloat16 g_a2lo[(size_t)N_TGT2 * 384];
__device__ __nv_bfloat16 g_w2hi[(size_t)F_HID * 384];
__device__ __nv_bfloat16 g_w2lo[(size_t)F_HID * 384];

// Layer-3 A: h2 ; W1
__device__ __nv_bfloat16 g_a3hi[(size_t)N_TGT2 * 192];
__device__ __nv_bfloat16 g_a3lo[(size_t)N_TGT2 * 192];
__device__ __nv_bfloat16 g_w3hi[(size_t)F_HID * 192];
__device__ __nv_bfloat16 g_w3lo[(size_t)F_HID * 192];

// Layer-4 A: relu(emb) ; W2
__device__ __nv_bfloat16 g_a4hi[(size_t)N_TGT2 * 192];
__device__ __nv_bfloat16 g_a4lo[(size_t)N_TGT2 * 192];
__device__ __nv_bfloat16 g_w4hi[(size_t)F_OUT * 192];
__device__ __nv_bfloat16 g_w4lo[(size_t)F_OUT * 192];

__device__ float g_h1[(size_t)N_TGT1 * F_HID];

// ---------------- bf16 split helpers ----------------
__device__ __forceinline__ void split1(float a, __nv_bfloat16& h, __nv_bfloat16& l) {
    h = __float2bfloat16_rn(a);
    l = __float2bfloat16_rn(a - __bfloat162float(h));
}

// ============ launch 1: convert x[:50000] + ALL weights + zero deg/ctr ============
#define XQ (N_TGT1 * 64)
__global__ void conv_all_kernel(const float* __restrict__ x,
                                const float* __restrict__ Wl1, const float* __restrict__ Wr1,
                                const float* __restrict__ Wl2, const float* __restrict__ Wr2,
                                const float* __restrict__ W1, const float* __restrict__ W2) {
    int i = blockIdx.x * blockDim.x + threadIdx.x;
    if (i < N_TGT1) g_deg1[i] = 0;
    if (i < N_TGT2) g_deg2[i] = 0;
    if (i < 2) g_ctr[i] = 0;

    const float* in; __nv_bfloat16* hi; __nv_bfloat16* lo;
    int q, c4n, lda, col0;
    if (i < XQ) { in = x; hi = g_ahi; lo = g_alo; q = i; c4n = 64; lda = 512; col0 = 256; }
    else {
        int j = i - XQ;
        if (j < 12288)      { in = Wl1; hi = g_whi;  lo = g_wlo;  q = j;          c4n = 64; lda = 512; col0 = 0; }
        else if (j < 24576) { in = Wr1; hi = g_whi;  lo = g_wlo;  q = j - 12288;  c4n = 64; lda = 512; col0 = 256; }
        else if (j < 33792) { in = Wl2; hi = g_w2hi; lo = g_w2lo; q = j - 24576;  c4n = 48; lda = 384; col0 = 0; }
        else if (j < 43008) { in = Wr2; hi = g_w2hi; lo = g_w2lo; q = j - 33792;  c4n = 48; lda = 384; col0 = 192; }
        else if (j < 52224) { in = W1;  hi = g_w3hi; lo = g_w3lo; q = j - 43008;  c4n = 48; lda = 192; col0 = 0; }
        else if (j < 58368) { in = W2;  hi = g_w4hi; lo = g_w4lo; q = j - 52224;  c4n = 48; lda = 192; col0 = 0; }
        else return;
    }
    int r = q / c4n, c = (q % c4n) << 2;
    float4 v = *(const float4*)(in + (size_t)r * (c4n * 4) + c);
    __nv_bfloat16 h0, h1, h2, h3, l0, l1, l2, l3;
    split1(v.x, h0, l0); split1(v.y, h1, l1);
    split1(v.z, h2, l2); split1(v.w, h3, l3);
    size_t o = (size_t)r * lda + col0 + c;
    *(__nv_bfloat162*)(hi + o)     = __nv_bfloat162(h0, h1);
    *(__nv_bfloat162*)(hi + o + 2) = __nv_bfloat162(h2, h3);
    *(__nv_bfloat162*)(lo + o)     = __nv_bfloat162(l0, l1);
    *(__nv_bfloat162*)(lo + o + 2) = __nv_bfloat162(l2, l3);
}

// ============ launch 2: histogram both edge lists ============
__global__ void hist_both_kernel(const int* __restrict__ ei1, const int* __restrict__ ei2) {
    int i = blockIdx.x * blockDim.x + threadIdx.x;
    if (i < E1) {
        atomicAdd(&g_deg1[ei1[E1 + i]], 1);
    } else if (i < E1 + E2) {
        int j = i - E1;
        atomicAdd(&g_deg2[ei2[E2 + j]], 1);
    }
}

// ============ launch 3: per-block scans; block base via atomic counter ============
__global__ void scan_block_both_kernel(int nb1) {
    const int* deg; int* off; int* pos; int* bsum; int n; int b; int list;
    if ((int)blockIdx.x < nb1) { deg = g_deg1; off = g_off1; pos = g_pos1; bsum = g_bsum1; n = N_TGT1; b = blockIdx.x; list = 0; }
    else { deg = g_deg2; off = g_off2; pos = g_pos2; bsum = g_bsum2; n = N_TGT2; b = blockIdx.x - nb1; list = 1; }
    __shared__ int wsum[16];
    int tid = threadIdx.x, lane = tid & 31, wid = tid >> 5;
    int i = b * 512 + tid;
    int v = (i < n) ? deg[i] : 0;
    int sc = v;
    #pragma unroll
    for (int o = 1; o < 32; o <<= 1) {
        int t = __shfl_up_sync(0xFFFFFFFFu, sc, o);
        if (lane >= o) sc += t;
    }
    if (lane == 31) wsum[wid] = sc;
    __syncthreads();
    if (wid == 0) {
        int ws = (lane < 16) ? wsum[lane] : 0;
        #pragma unroll
        for (int o = 1; o < 16; o <<= 1) {
            int t = __shfl_up_sync(0xFFFFFFFFu, ws, o);
            if (lane >= o) ws += t;
        }
        if (lane < 16) wsum[lane] = ws;
    }
    __syncthreads();
    int incl = sc + (wid ? wsum[wid - 1] : 0);
    if (i < n) { off[i + 1] = incl; pos[i] = incl - v; }  // block-local values
    if (tid == 511) {
        int base = atomicAdd(&g_ctr[list], incl);  // any order is valid
        bsum[b] = base;
    }
}

// ============ launch 4: fill CSR for both lists ============
__global__ void fill_both_kernel(const int* __restrict__ ei1, const int* __restrict__ ei2) {
    int i = blockIdx.x * blockDim.x + threadIdx.x;
    if (i < E1) {
        int t = ei1[E1 + i];
        int p = atomicAdd(&g_pos1[t], 1) + g_bsum1[t >> 9];
        g_idx1[p] = ei1[i];
    } else if (i < E1 + E2) {
        int j = i - E1;
        int t = ei2[E2 + j];
        int p = atomicAdd(&g_pos2[t], 1) + g_bsum2[t >> 9];
        g_idx2[p] = ei2[j];
    }
}

__device__ __forceinline__ int seg_beg(const int* off, const int* bsum, int w) {
    return (w & 511) ? off[w] + bsum[w >> 9] : bsum[w >> 9];
}
__device__ __forceinline__ int seg_end(const int* off, const int* bsum, int w) {
    return off[w + 1] + bsum[w >> 9];
}

// ============ launch 5: layer-1 segment mean, 2 warps/target, 4-edge unroll ============
__global__ void agg1_kernel(const float* __restrict__ feat) {
    int gw = (blockIdx.x * blockDim.x + threadIdx.x) >> 5;
    int lane = threadIdx.x & 31;
    if (gw >= N_TGT1 * 2) return;
    int w = gw >> 1, h = gw & 1;
    int slot = h * 32 + lane;
    int beg = seg_beg(g_off1, g_bsum1, w);
    int end = seg_end(g_off1, g_bsum1, w);
    float4 a = make_float4(0.f, 0.f, 0.f, 0.f);
    int e = beg;
    for (; e + 4 <= end; e += 4) {
        int i0 = g_idx1[e], i1 = g_idx1[e + 1], i2 = g_idx1[e + 2], i3 = g_idx1[e + 3];
        float4 v0 = __ldg((const float4*)(feat + (size_t)i0 * F_IN) + slot);
        float4 v1 = __ldg((const float4*)(feat + (size_t)i1 * F_IN) + slot);
        float4 v2 = __ldg((const float4*)(feat + (size_t)i2 * F_IN) + slot);
        float4 v3 = __ldg((const float4*)(feat + (size_t)i3 * F_IN) + slot);
        a.x += (v0.x + v1.x) + (v2.x + v3.x);
        a.y += (v0.y + v1.y) + (v2.y + v3.y);
        a.z += (v0.z + v1.z) + (v2.z + v3.z);
        a.w += (v0.w + v1.w) + (v2.w + v3.w);
    }
    for (; e < end; e++) {
        float4 v = __ldg((const float4*)(feat + (size_t)g_idx1[e] * F_IN) + slot);
        a.x += v.x; a.y += v.y; a.z += v.z; a.w += v.w;
    }
    int c = end - beg;
    float s = 1.0f / (float)(c > 1 ? c : 1);
    a.x *= s; a.y *= s; a.z *= s; a.w *= s;
    __nv_bfloat16 hh[4], ll[4];
    split1(a.x, hh[0], ll[0]); split1(a.y, hh[1], ll[1]);
    split1(a.z, hh[2], ll[2]); split1(a.w, hh[3], ll[3]);
    size_t o = (size_t)w * 512 + slot * 4;
    *(__nv_bfloat162*)(g_ahi + o)     = __nv_bfloat162(hh[0], hh[1]);
    *(__nv_bfloat162*)(g_ahi + o + 2) = __nv_bfloat162(hh[2], hh[3]);
    *(__nv_bfloat162*)(g_alo + o)     = __nv_bfloat162(ll[0], ll[1]);
    *(__nv_bfloat162*)(g_alo + o + 2) = __nv_bfloat162(ll[2], ll[3]);
}

// ============ layer-2 segment mean (F=192) ============
__global__ void agg2_kernel(const float* __restrict__ feat) {
    int w = (blockIdx.x * blockDim.x + threadIdx.x) >> 5;
    int lane = threadIdx.x & 31;
    if (w >= N_TGT2) return;
    int beg = seg_beg(g_off2, g_bsum2, w);
    int end = seg_end(g_off2, g_bsum2, w);
    bool two = lane < 16;
    float4 a0 = make_float4(0.f, 0.f, 0.f, 0.f);
    float4 a1 = make_float4(0.f, 0.f, 0.f, 0.f);
    int e = beg;
    for (; e + 2 <= end; e += 2) {
        int i0 = g_idx2[e], i1 = g_idx2[e + 1];
        const float4* r0 = (const float4*)(feat + (size_t)i0 * F_HID);
        const float4* r1 = (const float4*)(feat + (size_t)i1 * F_HID);
        float4 v0 = __ldg(r0 + lane);
        float4 v1 = __ldg(r1 + lane);
        if (two) {
            float4 u0 = __ldg(r0 + lane + 32);
            float4 u1 = __ldg(r1 + lane + 32);
            a1.x += u0.x + u1.x; a1.y += u0.y + u1.y;
            a1.z += u0.z + u1.z; a1.w += u0.w + u1.w;
        }
        a0.x += v0.x + v1.x; a0.y += v0.y + v1.y;
        a0.z += v0.z + v1.z; a0.w += v0.w + v1.w;
    }
    if (e < end) {
        const float4* r = (const float4*)(feat + (size_t)g_idx2[e] * F_HID);
        float4 v = __ldg(r + lane);
        a0.x += v.x; a0.y += v.y; a0.z += v.z; a0.w += v.w;
        if (two) {
            float4 u = __ldg(r + lane + 32);
            a1.x += u.x; a1.y += u.y; a1.z += u.z; a1.w += u.w;
        }
    }
    int c = end - beg;
    float s = 1.0f / (float)(c > 1 ? c : 1);
    a0.x *= s; a0.y *= s; a0.z *= s; a0.w *= s;
    __nv_bfloat16 h[4], l[4];
    split1(a0.x, h[0], l[0]); split1(a0.y, h[1], l[1]);
    split1(a0.z, h[2], l[2]); split1(a0.w, h[3], l[3]);
    size_t o0 = (size_t)w * 384 + lane * 4;
    *(__nv_bfloat162*)(g_a2hi + o0)     = __nv_bfloat162(h[0], h[1]);
    *(__nv_bfloat162*)(g_a2hi + o0 + 2) = __nv_bfloat162(h[2], h[3]);
    *(__nv_bfloat162*)(g_a2lo + o0)     = __nv_bfloat162(l[0], l[1]);
    *(__nv_bfloat162*)(g_a2lo + o0 + 2) = __nv_bfloat162(l[2], l[3]);
    if (two) {
        a1.x *= s; a1.y *= s; a1.z *= s; a1.w *= s;
        split1(a1.x, h[0], l[0]); split1(a1.y, h[1], l[1]);
        split1(a1.z, h[2], l[2]); split1(a1.w, h[3], l[3]);
        size_t o1 = (size_t)w * 384 + (lane + 32) * 4;
        *(__nv_bfloat162*)(g_a2hi + o1)     = __nv_bfloat162(h[0], h[1]);
        *(__nv_bfloat162*)(g_a2hi + o1 + 2) = __nv_bfloat162(h[2], h[3]);
        *(__nv_bfloat162*)(g_a2lo + o1)     = __nv_bfloat162(l[0], l[1]);
        *(__nv_bfloat162*)(g_a2lo + o1 + 2) = __nv_bfloat162(l[2], l[3]);
    }
}

// ================= mma.sync bf16 split GEMM =================
#define ROWB 80

__device__ __forceinline__ uint32_t smem_u32(const void* p) {
    uint32_t a;
    asm("{ .reg .u64 t; cvta.to.shared.u64 t, %1; cvt.u32.u64 %0, t; }" : "=r"(a) : "l"(p));
    return a;
}
__device__ __forceinline__ void cp16(uint32_t s, const void* g) {
    asm volatile("cp.async.cg.shared.global [%0], [%1], 16;" :: "r"(s), "l"(g));
}
__device__ __forceinline__ void cp_commit() { asm volatile("cp.async.commit_group;"); }
__device__ __forceinline__ void cp_wait1() { asm volatile("cp.async.wait_group 1;"); }
__device__ __forceinline__ void ldm4(uint32_t* r, uint32_t a) {
    asm volatile("ldmatrix.sync.aligned.m8n8.x4.shared.b16 {%0,%1,%2,%3}, [%4];"
                 : "=r"(r[0]), "=r"(r[1]), "=r"(r[2]), "=r"(r[3]) : "r"(a));
}
__device__ __forceinline__ void mma_bf16(float* c, const uint32_t* a, uint32_t b0, uint32_t b1) {
    asm volatile("mma.sync.aligned.m16n8k16.row.col.f32.bf16.bf16.f32 "
                 "{%0,%1,%2,%3},{%4,%5,%6,%7},{%8,%9},{%0,%1,%2,%3};"
                 : "+f"(c[0]), "+f"(c[1]), "+f"(c[2]), "+f"(c[3])
                 : "r"(a[0]), "r"(a[1]), "r"(a[2]), "r"(a[3]), "r"(b0), "r"(b1));
}

// mainloop body shared by both gemm kernels (via macro-free duplication in template)
template <int NN>
__device__ __forceinline__ void gemm_mainloop(
    uint32_t smb, int tid, int w, int lane, int m0, int M, int K,
    const __nv_bfloat16* ahi, const __nv_bfloat16* alo,
    const __nv_bfloat16* whi, const __nv_bfloat16* wlo,
    float acc[2][2 * (NN / 32)][4])
{
    constexpr int NJ = NN / 32;
    constexpr int NBI = NN / 64;
    constexpr int SAHI = 0;
    constexpr int SALO = 128 * ROWB;
    constexpr int SBHI = 256 * ROWB;
    constexpr int SBLO = (256 + NN) * ROWB;
    constexpr int BUF = (256 + 2 * NN) * ROWB;

    int wm = (w >> 1) * 32;
    int wn = (w & 1) * (NN / 2);
    int arow = tid >> 2;
    int aseg = (tid & 3) * 16;
    int asegk = (tid & 3) * 8;
    int chunks = K >> 5;

    auto load_chunk = [&](int c) {
        int k0 = c * 32;
        uint32_t base = smb + (c & 1) * BUF;
        #pragma unroll
        for (int i = 0; i < 2; i++) {
            int row = arow + i * 64;
            int gr = m0 + row; if (gr >= M) gr = M - 1;
            size_t go = (size_t)gr * K + k0 + asegk;
            uint32_t so = row * ROWB + aseg;
            cp16(base + SAHI + so, ahi + go);
            cp16(base + SALO + so, alo + go);
        }
        #pragma unroll
        for (int i = 0; i < NBI; i++) {
            int row = arow + i * 64;
            size_t go = (size_t)row * K + k0 + asegk;
            uint32_t so = row * ROWB + aseg;
            cp16(base + SBHI + so, whi + go);
            cp16(base + SBLO + so, wlo + go);
        }
    };

    int grp = lane >> 3, lr = lane & 7;
    int a_row_off = lr + (grp & 1) * 8;
    int a_k_off = (grp >> 1) * 8;
    int b_row_off = (grp & 2) * 4 + lr;
    int b_k_off = (grp & 1) * 8;

    load_chunk(0);
    cp_commit();

    #pragma unroll 1
    for (int c = 0; c < chunks; c++) {
        if (c + 1 < chunks) load_chunk(c + 1);
        cp_commit();
        cp_wait1();
        __syncthreads();

        uint32_t base = smb + (c & 1) * BUF;
        #pragma unroll
        for (int s = 0; s < 2; s++) {
            uint32_t ah[2][4], al[2][4];
            #pragma unroll
            for (int mt = 0; mt < 2; mt++) {
                uint32_t ra = (wm + mt * 16 + a_row_off) * ROWB + (s * 16 + a_k_off) * 2;
                ldm4(ah[mt], base + SAHI + ra);
                ldm4(al[mt], base + SALO + ra);
            }
            #pragma unroll
            for (int j = 0; j < NJ; j++) {
                uint32_t rb = (wn + j * 16 + b_row_off) * ROWB + (s * 16 + b_k_off) * 2;
                uint32_t bh[4], bl[4];
                ldm4(bh, base + SBHI + rb);
                ldm4(bl, base + SBLO + rb);
                #pragma unroll
                for (int mt = 0; mt < 2; mt++) {
                    mma_bf16(acc[mt][2 * j],     ah[mt], bh[0], bh[1]);
                    mma_bf16(acc[mt][2 * j],     ah[mt], bl[0], bl[1]);
                    mma_bf16(acc[mt][2 * j],     al[mt], bh[0], bh[1]);
                    mma_bf16(acc[mt][2 * j + 1], ah[mt], bh[2], bh[3]);
                    mma_bf16(acc[mt][2 * j + 1], ah[mt], bl[2], bl[3]);
                    mma_bf16(acc[mt][2 * j + 1], al[mt], bh[2], bh[3]);
                }
            }
        }
        __syncthreads();
    }
}

template <int NN>
__global__ __launch_bounds__(256) void mmagemm_kernel(
    const __nv_bfloat16* __restrict__ ahi, const __nv_bfloat16* __restrict__ alo,
    const __nv_bfloat16* __restrict__ whi, const __nv_bfloat16* __restrict__ wlo,
    const float* __restrict__ bias, int M, int K,
    float* __restrict__ Cf32, int relu_f32,
    __nv_bfloat16* __restrict__ shi, __nv_bfloat16* __restrict__ slo,
    int s_lda, int s_col0, int s_maxrow)
{
    extern __shared__ char sm[];
    uint32_t smb = smem_u32(sm);
    int tid = threadIdx.x;
    int w = tid >> 5, lane = tid & 31;
    int m0 = blockIdx.x * 128;
    int wm = (w >> 1) * 32;
    int wn = (w & 1) * (NN / 2);

    float acc[2][2 * (NN / 32)][4];
    #pragma unroll
    for (int i = 0; i < 2; i++)
        #pragma unroll
        for (int j = 0; j < 2 * (NN / 32); j++)
            #pragma unroll
            for (int k = 0; k < 4; k++) acc[i][j][k] = 0.f;

    gemm_mainloop<NN>(smb, tid, w, lane, m0, M, K, ahi, alo, whi, wlo, acc);

    int g = lane >> 2, t = lane & 3;
    #pragma unroll
    for (int mt = 0; mt < 2; mt++) {
        int r0 = m0 + wm + mt * 16 + g;
        #pragma unroll
        for (int j = 0; j < 2 * (NN / 32); j++) {
            int col = wn + j * 8 + 2 * t;
            float2 bv = *(const float2*)(bias + col);
            float o0 = acc[mt][j][0] + bv.x, o1 = acc[mt][j][1] + bv.y;
            float o2 = acc[mt][j][2] + bv.x, o3 = acc[mt][j][3] + bv.y;
            if (Cf32) {
                float p0 = o0, p1 = o1, p2 = o2, p3 = o3;
                if (relu_f32) {
                    p0 = fmaxf(p0, 0.f); p1 = fmaxf(p1, 0.f);
                    p2 = fmaxf(p2, 0.f); p3 = fmaxf(p3, 0.f);
                }
                if (r0 < M)     *(float2*)(Cf32 + (size_t)r0 * NN + col)       = make_float2(p0, p1);
                if (r0 + 8 < M) *(float2*)(Cf32 + (size_t)(r0 + 8) * NN + col) = make_float2(p2, p3);
            }
            if (shi) {
                o0 = fmaxf(o0, 0.f); o1 = fmaxf(o1, 0.f);
                o2 = fmaxf(o2, 0.f); o3 = fmaxf(o3, 0.f);
                __nv_bfloat16 h0, h1, h2, h3, l0, l1, l2, l3;
                split1(o0, h0, l0); split1(o1, h1, l1);
                split1(o2, h2, l2); split1(o3, h3, l3);
                if (r0 < s_maxrow) {
                    size_t o = (size_t)r0 * s_lda + s_col0 + col;
                    *(__nv_bfloat162*)(shi + o) = __nv_bfloat162(h0, h1);
                    *(__nv_bfloat162*)(slo + o) = __nv_bfloat162(l0, l1);
                }
                if (r0 + 8 < s_maxrow) {
                    size_t o = (size_t)(r0 + 8) * s_lda + s_col0 + col;
                    *(__nv_bfloat162*)(shi + o) = __nv_bfloat162(h2, h3);
                    *(__nv_bfloat162*)(slo + o) = __nv_bfloat162(l2, l3);
                }
            }
        }
    }
}

// ============ gemm (NN=128) fused with log_softmax epilogue ============
__global__ __launch_bounds__(256) void gemm_softmax_kernel(
    const __nv_bfloat16* __restrict__ ahi, const __nv_bfloat16* __restrict__ alo,
    const __nv_bfloat16* __restrict__ whi, const __nv_bfloat16* __restrict__ wlo,
    const float* __restrict__ bias, int M, int K,
    float* __restrict__ out)
{
    extern __shared__ char sm[];
    uint32_t smb = smem_u32(sm);
    int tid = threadIdx.x;
    int w = tid >> 5, lane = tid & 31;
    int m0 = blockIdx.x * 128;
    int wm = (w >> 1) * 32;
    int wn = (w & 1) * 64;

    float acc[2][8][4];
    #pragma unroll
    for (int i = 0; i < 2; i++)
        #pragma unroll
        for (int j = 0; j < 8; j++)
            #pragma unroll
            for (int k = 0; k < 4; k++) acc[i][j][k] = 0.f;

    gemm_mainloop<128>(smb, tid, w, lane, m0, M, K, ahi, alo, whi, wlo, acc);

    // stage logits (+bias) into smem: 128 rows x 132 floats (528B stride, 16B-aligned)
    float* es = (float*)sm;
    int g = lane >> 2, t = lane & 3;
    #pragma unroll
    for (int mt = 0; mt < 2; mt++) {
        int r = wm + mt * 16 + g;
        #pragma unroll
        for (int j = 0; j < 8; j++) {
            int col = wn + j * 8 + 2 * t;
            float2 bv = *(const float2*)(bias + col);
            *(float2*)&es[(r)     * 132 + col] = make_float2(acc[mt][j][0] + bv.x, acc[mt][j][1] + bv.y);
            *(float2*)&es[(r + 8) * 132 + col] = make_float2(acc[mt][j][2] + bv.x, acc[mt][j][3] + bv.y);
        }
    }
    __syncthreads();

    // warp-per-row log_softmax: warp w handles rows w*16 .. w*16+15
    for (int rr = 0; rr < 16; rr++) {
        int r = w * 16 + rr;
        int gr = m0 + r;
        if (gr >= M) break;
        float4 v = *(float4*)&es[r * 132 + lane * 4];
        float m = fmaxf(fmaxf(v.x, v.y), fmaxf(v.z, v.w));
        #pragma unroll
        for (int o = 16; o > 0; o >>= 1) m = fmaxf(m, __shfl_xor_sync(0xFFFFFFFFu, m, o));
        float s = expf(v.x - m) + expf(v.y - m) + expf(v.z - m) + expf(v.w - m);
        #pragma unroll
        for (int o = 16; o > 0; o >>= 1) s += __shfl_xor_sync(0xFFFFFFFFu, s, o);
        float l = m + logf(s);
        *(float4*)(out + (size_t)gr * F_OUT + lane * 4) =
            make_float4(v.x - l, v.y - l, v.z - l, v.w - l);
    }
}

// ---------------- launch ----------------
extern "C" void kernel_launch(void* const* d_in, const int* in_sizes, int n_in,
                              void* d_out, int out_size) {
    const float* x   = (const float*)d_in[0];
    const int*   ei1 = (const int*)d_in[1];
    const int*   ei2 = (const int*)d_in[2];
    const float* Wl1 = (const float*)d_in[3];
    const float* bl1 = (const float*)d_in[4];
    const float* Wr1 = (const float*)d_in[5];
    const float* Wl2 = (const float*)d_in[6];
    const float* bl2 = (const float*)d_in[7];
    const float* Wr2 = (const float*)d_in[8];
    const float* W1  = (const float*)d_in[9];
    const float* b1  = (const float*)d_in[10];
    const float* W2  = (const float*)d_in[11];
    const float* b2  = (const float*)d_in[12];

    float* out = (float*)d_out;
    float* out_ls  = out;                           // [10000,128]
    float* out_emb = out + (size_t)N_TGT2 * F_OUT;  // [10000,192]

    float* h1;
    __nv_bfloat16 *ahi, *alo, *whi, *wlo;
    __nv_bfloat16 *a2hi, *a2lo, *w2hi, *w2lo;
    __nv_bfloat16 *a3hi, *a3lo, *w3hi, *w3lo;
    __nv_bfloat16 *a4hi, *a4lo, *w4hi, *w4lo;
    cudaGetSymbolAddress((void**)&h1, g_h1);
    cudaGetSymbolAddress((void**)&ahi, g_ahi);
    cudaGetSymbolAddress((void**)&alo, g_alo);
    cudaGetSymbolAddress((void**)&whi, g_whi);
    cudaGetSymbolAddress((void**)&wlo, g_wlo);
    cudaGetSymbolAddress((void**)&a2hi, g_a2hi);
    cudaGetSymbolAddress((void**)&a2lo, g_a2lo);
    cudaGetSymbolAddress((void**)&w2hi, g_w2hi);
    cudaGetSymbolAddress((void**)&w2lo, g_w2lo);
    cudaGetSymbolAddress((void**)&a3hi, g_a3hi);
    cudaGetSymbolAddress((void**)&a3lo, g_a3lo);
    cudaGetSymbolAddress((void**)&w3hi, g_w3hi);
    cudaGetSymbolAddress((void**)&w3lo, g_w3lo);
    cudaGetSymbolAddress((void**)&a4hi, g_a4hi);
    cudaGetSymbolAddress((void**)&a4lo, g_a4lo);
    cudaGetSymbolAddress((void**)&w4hi, g_w4hi);
    cudaGetSymbolAddress((void**)&w4lo, g_w4lo);

    const int SMEM192 = 2 * (256 + 2 * 192) * ROWB;  // 102400
    const int SMEM128 = 2 * (256 + 2 * 128) * ROWB;  // 81920
    cudaFuncSetAttribute(mmagemm_kernel<192>, cudaFuncAttributeMaxDynamicSharedMemorySize, SMEM192);
    cudaFuncSetAttribute(gemm_softmax_kernel, cudaFuncAttributeMaxDynamicSharedMemorySize, SMEM128);

    int nb1 = (N_TGT1 + 511) / 512;  // 98
    int nb2 = (N_TGT2 + 511) / 512;  // 20

    // 1: all converts + zero
    conv_all_kernel<<<(XQ + 58368 + 255) / 256, 256>>>(x, Wl1, Wr1, Wl2, Wr2, W1, W2);
    // 2-4: CSR build
    hist_both_kernel<<<(E1 + E2 + 255) / 256, 256>>>(ei1, ei2);
    scan_block_both_kernel<<<nb1 + nb2, 512>>>(nb1);
    fill_both_kernel<<<(E1 + E2 + 255) / 256, 256>>>(ei1, ei2);

    // 5: layer-1 aggregation
    agg1_kernel<<<(N_TGT1 * 2 * 32 + 255) / 256, 256>>>(x);

    // 6: layer-1 GEMM -> h1 fp32 (relu) + h1 split rows<10000
    mmagemm_kernel<192><<<(N_TGT1 + 127) / 128, 256, SMEM192>>>(
        ahi, alo, whi, wlo, bl1, N_TGT1, 512,
        h1, 1,
        a2hi, a2lo, 384, 192, N_TGT2);

    // 7: layer-2 aggregation
    agg2_kernel<<<(N_TGT2 * 32 + 255) / 256, 256>>>(h1);

    // 8: layer-2 GEMM -> h2 split
    mmagemm_kernel<192><<<(N_TGT2 + 127) / 128, 256, SMEM192>>>(
        a2hi, a2lo, w2hi, w2lo, bl2, N_TGT2, 384,
        (float*)0, 0,
        a3hi, a3lo, 192, 0, N_TGT2);

    // 9: layer-3 GEMM -> embedding fp32 + relu(emb) split
    mmagemm_kernel<192><<<(N_TGT2 + 127) / 128, 256, SMEM192>>>(
        a3hi, a3lo, w3hi, w3lo, b1, N_TGT2, 192,
        out_emb, 0,
        a4hi, a4lo, 192, 0, N_TGT2);

    // 10: layer-4 GEMM + log_softmax -> out_ls
    gemm_softmax_kernel<<<(N_TGT2 + 127) / 128, 256, SMEM128>>>(
        a4hi, a4lo, w4hi, w4lo, b2, N_TGT2, 192, out_ls);
}

// round 8
// speedup vs baseline: 1.7358x; 1.0755x over previous
#include <cuda_runtime.h>
#include <cuda_fp16.h>
#include <math.h>
#include <stdint.h>

#define N_SRC1 200000
#define N_TGT1 50000
#define N_TGT2 10000
#define E1 1000000
#define E2 300000
#define F_IN 256
#define F_HID 192
#define F_OUT 128

// ---------------- scratch (device globals; allocation is forbidden) ----------------
__device__ int g_deg1[N_TGT1];
__device__ int g_off1[N_TGT1 + 1];
__device__ int g_pos1[N_TGT1];
__device__ int g_idx1[E1];

__device__ int g_deg2[N_TGT2];
__device__ int g_off2[N_TGT2 + 1];
__device__ int g_pos2[N_TGT2];
__device__ int g_idx2[E2];

__device__ int g_bsum1[256];
__device__ int g_bsum2[256];
__device__ int g_ctr[2];

// Layer-1: A = [agg1 | x[:50000]] fp16 hi/lo, K=512 ; W1cat hi only (2-term gemm)
__device__ __half g_ahi[(size_t)N_TGT1 * 512];
__device__ __half g_alo[(size_t)N_TGT1 * 512];
__device__ __half g_whi[(size_t)F_HID * 512];

// Layer-2: A = [agg2 | h1[:10000]] K=384 ; W2cat hi+lo (3-term)
__device__ __half g_a2hi[(size_t)N_TGT2 * 384];
__device__ __half g_a2lo[(size_t)N_TGT2 * 384];
__device__ __half g_w2hi[(size_t)F_HID * 384];
__device__ __half g_w2lo[(size_t)F_HID * 384];

// Layer-3: h2 ; W1 hi+lo
__device__ __half g_a3hi[(size_t)N_TGT2 * 192];
__device__ __half g_a3lo[(size_t)N_TGT2 * 192];
__device__ __half g_w3hi[(size_t)F_HID * 192];
__device__ __half g_w3lo[(size_t)F_HID * 192];

// Layer-4: relu(emb) ; W2 hi+lo
__device__ __half g_a4hi[(size_t)N_TGT2 * 192];
__device__ __half g_a4lo[(size_t)N_TGT2 * 192];
__device__ __half g_w4hi[(size_t)F_OUT * 192];
__device__ __half g_w4lo[(size_t)F_OUT * 192];

__device__ float g_h1[(size_t)N_TGT1 * F_HID];

// ---------------- fp16 split helpers ----------------
__device__ __forceinline__ void split1(float a, __half& h, __half& l) {
    h = __float2half_rn(a);
    l = __float2half_rn(a - __half2float(h));
}

// ============ launch 1: convert x[:50000] + ALL weights + zero deg/ctr ============
#define XQ (N_TGT1 * 64)
__global__ void conv_all_kernel(const float* __restrict__ x,
                                const float* __restrict__ Wl1, const float* __restrict__ Wr1,
                                const float* __restrict__ Wl2, const float* __restrict__ Wr2,
                                const float* __restrict__ W1, const float* __restrict__ W2) {
    int i = blockIdx.x * blockDim.x + threadIdx.x;
    if (i < N_TGT1) g_deg1[i] = 0;
    if (i < N_TGT2) g_deg2[i] = 0;
    if (i < 2) g_ctr[i] = 0;

    const float* in; __half* hi; __half* lo;
    int q, c4n, lda, col0;
    if (i < XQ) { in = x; hi = g_ahi; lo = g_alo; q = i; c4n = 64; lda = 512; col0 = 256; }
    else {
        int j = i - XQ;
        if (j < 12288)      { in = Wl1; hi = g_whi;  lo = (__half*)0; q = j;          c4n = 64; lda = 512; col0 = 0; }
        else if (j < 24576) { in = Wr1; hi = g_whi;  lo = (__half*)0; q = j - 12288;  c4n = 64; lda = 512; col0 = 256; }
        else if (j < 33792) { in = Wl2; hi = g_w2hi; lo = g_w2lo;     q = j - 24576;  c4n = 48; lda = 384; col0 = 0; }
        else if (j < 43008) { in = Wr2; hi = g_w2hi; lo = g_w2lo;     q = j - 33792;  c4n = 48; lda = 384; col0 = 192; }
        else if (j < 52224) { in = W1;  hi = g_w3hi; lo = g_w3lo;     q = j - 43008;  c4n = 48; lda = 192; col0 = 0; }
        else if (j < 58368) { in = W2;  hi = g_w4hi; lo = g_w4lo;     q = j - 52224;  c4n = 48; lda = 192; col0 = 0; }
        else return;
    }
    int r = q / c4n, c = (q % c4n) << 2;
    float4 v = *(const float4*)(in + (size_t)r * (c4n * 4) + c);
    __half h0, h1, h2, h3, l0, l1, l2, l3;
    split1(v.x, h0, l0); split1(v.y, h1, l1);
    split1(v.z, h2, l2); split1(v.w, h3, l3);
    size_t o = (size_t)r * lda + col0 + c;
    *(__half2*)(hi + o)     = __halves2half2(h0, h1);
    *(__half2*)(hi + o + 2) = __halves2half2(h2, h3);
    if (lo) {
        *(__half2*)(lo + o)     = __halves2half2(l0, l1);
        *(__half2*)(lo + o + 2) = __halves2half2(l2, l3);
    }
}

// ============ launch 2: histogram both edge lists, 4 edges/thread ============
__global__ void hist_both_kernel(const int* __restrict__ ei1, const int* __restrict__ ei2) {
    int i = blockIdx.x * blockDim.x + threadIdx.x;
    const int n1 = E1 / 4, n2 = E2 / 4;
    if (i < n1) {
        int4 t = *(const int4*)(ei1 + E1 + i * 4);
        atomicAdd(&g_deg1[t.x], 1);
        atomicAdd(&g_deg1[t.y], 1);
        atomicAdd(&g_deg1[t.z], 1);
        atomicAdd(&g_deg1[t.w], 1);
    } else if (i < n1 + n2) {
        int j = i - n1;
        int4 t = *(const int4*)(ei2 + E2 + j * 4);
        atomicAdd(&g_deg2[t.x], 1);
        atomicAdd(&g_deg2[t.y], 1);
        atomicAdd(&g_deg2[t.z], 1);
        atomicAdd(&g_deg2[t.w], 1);
    }
}

// ============ launch 3: per-block scans; block base via atomic counter ============
__global__ void scan_block_both_kernel(int nb1) {
    const int* deg; int* off; int* pos; int* bsum; int n; int b; int list;
    if ((int)blockIdx.x < nb1) { deg = g_deg1; off = g_off1; pos = g_pos1; bsum = g_bsum1; n = N_TGT1; b = blockIdx.x; list = 0; }
    else { deg = g_deg2; off = g_off2; pos = g_pos2; bsum = g_bsum2; n = N_TGT2; b = blockIdx.x - nb1; list = 1; }
    __shared__ int wsum[16];
    int tid = threadIdx.x, lane = tid & 31, wid = tid >> 5;
    int i = b * 512 + tid;
    int v = (i < n) ? deg[i] : 0;
    int sc = v;
    #pragma unroll
    for (int o = 1; o < 32; o <<= 1) {
        int t = __shfl_up_sync(0xFFFFFFFFu, sc, o);
        if (lane >= o) sc += t;
    }
    if (lane == 31) wsum[wid] = sc;
    __syncthreads();
    if (wid == 0) {
        int ws = (lane < 16) ? wsum[lane] : 0;
        #pragma unroll
        for (int o = 1; o < 16; o <<= 1) {
            int t = __shfl_up_sync(0xFFFFFFFFu, ws, o);
            if (lane >= o) ws += t;
        }
        if (lane < 16) wsum[lane] = ws;
    }
    __syncthreads();
    int incl = sc + (wid ? wsum[wid - 1] : 0);
    if (i < n) { off[i + 1] = incl; pos[i] = incl - v; }
    if (tid == 511) {
        int base = atomicAdd(&g_ctr[list], incl);
        bsum[b] = base;
    }
}

// ============ launch 4: fill CSR, 4 edges/thread ============
__global__ void fill_both_kernel(const int* __restrict__ ei1, const int* __restrict__ ei2) {
    int i = blockIdx.x * blockDim.x + threadIdx.x;
    const int n1 = E1 / 4, n2 = E2 / 4;
    if (i < n1) {
        int4 t = *(const int4*)(ei1 + E1 + i * 4);
        int4 s = *(const int4*)(ei1 + i * 4);
        int p0 = atomicAdd(&g_pos1[t.x], 1) + g_bsum1[t.x >> 9];
        int p1 = atomicAdd(&g_pos1[t.y], 1) + g_bsum1[t.y >> 9];
        int p2 = atomicAdd(&g_pos1[t.z], 1) + g_bsum1[t.z >> 9];
        int p3 = atomicAdd(&g_pos1[t.w], 1) + g_bsum1[t.w >> 9];
        g_idx1[p0] = s.x; g_idx1[p1] = s.y; g_idx1[p2] = s.z; g_idx1[p3] = s.w;
    } else if (i < n1 + n2) {
        int j = i - n1;
        int4 t = *(const int4*)(ei2 + E2 + j * 4);
        int4 s = *(const int4*)(ei2 + j * 4);
        int p0 = atomicAdd(&g_pos2[t.x], 1) + g_bsum2[t.x >> 9];
        int p1 = atomicAdd(&g_pos2[t.y], 1) + g_bsum2[t.y >> 9];
        int p2 = atomicAdd(&g_pos2[t.z], 1) + g_bsum2[t.z >> 9];
        int p3 = atomicAdd(&g_pos2[t.w], 1) + g_bsum2[t.w >> 9];
        g_idx2[p0] = s.x; g_idx2[p1] = s.y; g_idx2[p2] = s.z; g_idx2[p3] = s.w;
    }
}

__device__ __forceinline__ int seg_beg(const int* off, const int* bsum, int w) {
    return (w & 511) ? off[w] + bsum[w >> 9] : bsum[w >> 9];
}
__device__ __forceinline__ int seg_end(const int* off, const int* bsum, int w) {
    return off[w + 1] + bsum[w >> 9];
}

// ============ launch 5: layer-1 segment mean, 2 warps/target, 4-edge unroll ============
__global__ void agg1_kernel(const float* __restrict__ feat) {
    int gw = (blockIdx.x * blockDim.x + threadIdx.x) >> 5;
    int lane = threadIdx.x & 31;
    if (gw >= N_TGT1 * 2) return;
    int w = gw >> 1, h = gw & 1;
    int slot = h * 32 + lane;
    int beg = seg_beg(g_off1, g_bsum1, w);
    int end = seg_end(g_off1, g_bsum1, w);
    float4 a = make_float4(0.f, 0.f, 0.f, 0.f);
    int e = beg;
    for (; e + 4 <= end; e += 4) {
        int i0 = g_idx1[e], i1 = g_idx1[e + 1], i2 = g_idx1[e + 2], i3 = g_idx1[e + 3];
        float4 v0 = __ldg((const float4*)(feat + (size_t)i0 * F_IN) + slot);
        float4 v1 = __ldg((const float4*)(feat + (size_t)i1 * F_IN) + slot);
        float4 v2 = __ldg((const float4*)(feat + (size_t)i2 * F_IN) + slot);
        float4 v3 = __ldg((const float4*)(feat + (size_t)i3 * F_IN) + slot);
        a.x += (v0.x + v1.x) + (v2.x + v3.x);
        a.y += (v0.y + v1.y) + (v2.y + v3.y);
        a.z += (v0.z + v1.z) + (v2.z + v3.z);
        a.w += (v0.w + v1.w) + (v2.w + v3.w);
    }
    for (; e < end; e++) {
        float4 v = __ldg((const float4*)(feat + (size_t)g_idx1[e] * F_IN) + slot);
        a.x += v.x; a.y += v.y; a.z += v.z; a.w += v.w;
    }
    int c = end - beg;
    float s = 1.0f / (float)(c > 1 ? c : 1);
    a.x *= s; a.y *= s; a.z *= s; a.w *= s;
    __half hh[4], ll[4];
    split1(a.x, hh[0], ll[0]); split1(a.y, hh[1], ll[1]);
    split1(a.z, hh[2], ll[2]); split1(a.w, hh[3], ll[3]);
    size_t o = (size_t)w * 512 + slot * 4;
    *(__half2*)(g_ahi + o)     = __halves2half2(hh[0], hh[1]);
    *(__half2*)(g_ahi + o + 2) = __halves2half2(hh[2], hh[3]);
    *(__half2*)(g_alo + o)     = __halves2half2(ll[0], ll[1]);
    *(__half2*)(g_alo + o + 2) = __halves2half2(ll[2], ll[3]);
}

// ============ layer-2 segment mean (F=192) ============
__global__ void agg2_kernel(const float* __restrict__ feat) {
    int w = (blockIdx.x * blockDim.x + threadIdx.x) >> 5;
    int lane = threadIdx.x & 31;
    if (w >= N_TGT2) return;
    int beg = seg_beg(g_off2, g_bsum2, w);
    int end = seg_end(g_off2, g_bsum2, w);
    bool two = lane < 16;
    float4 a0 = make_float4(0.f, 0.f, 0.f, 0.f);
    float4 a1 = make_float4(0.f, 0.f, 0.f, 0.f);
    int e = beg;
    for (; e + 2 <= end; e += 2) {
        int i0 = g_idx2[e], i1 = g_idx2[e + 1];
        const float4* r0 = (const float4*)(feat + (size_t)i0 * F_HID);
        const float4* r1 = (const float4*)(feat + (size_t)i1 * F_HID);
        float4 v0 = __ldg(r0 + lane);
        float4 v1 = __ldg(r1 + lane);
        if (two) {
            float4 u0 = __ldg(r0 + lane + 32);
            float4 u1 = __ldg(r1 + lane + 32);
            a1.x += u0.x + u1.x; a1.y += u0.y + u1.y;
            a1.z += u0.z + u1.z; a1.w += u0.w + u1.w;
        }
        a0.x += v0.x + v1.x; a0.y += v0.y + v1.y;
        a0.z += v0.z + v1.z; a0.w += v0.w + v1.w;
    }
    if (e < end) {
        const float4* r = (const float4*)(feat + (size_t)g_idx2[e] * F_HID);
        float4 v = __ldg(r + lane);
        a0.x += v.x; a0.y += v.y; a0.z += v.z; a0.w += v.w;
        if (two) {
            float4 u = __ldg(r + lane + 32);
            a1.x += u.x; a1.y += u.y; a1.z += u.z; a1.w += u.w;
        }
    }
    int c = end - beg;
    float s = 1.0f / (float)(c > 1 ? c : 1);
    a0.x *= s; a0.y *= s; a0.z *= s; a0.w *= s;
    __half h[4], l[4];
    split1(a0.x, h[0], l[0]); split1(a0.y, h[1], l[1]);
    split1(a0.z, h[2], l[2]); split1(a0.w, h[3], l[3]);
    size_t o0 = (size_t)w * 384 + lane * 4;
    *(__half2*)(g_a2hi + o0)     = __halves2half2(h[0], h[1]);
    *(__half2*)(g_a2hi + o0 + 2) = __halves2half2(h[2], h[3]);
    *(__half2*)(g_a2lo + o0)     = __halves2half2(l[0], l[1]);
    *(__half2*)(g_a2lo + o0 + 2) = __halves2half2(l[2], l[3]);
    if (two) {
        a1.x *= s; a1.y *= s; a1.z *= s; a1.w *= s;
        split1(a1.x, h[0], l[0]); split1(a1.y, h[1], l[1]);
        split1(a1.z, h[2], l[2]); split1(a1.w, h[3], l[3]);
        size_t o1 = (size_t)w * 384 + (lane + 32) * 4;
        *(__half2*)(g_a2hi + o1)     = __halves2half2(h[0], h[1]);
        *(__half2*)(g_a2hi + o1 + 2) = __halves2half2(h[2], h[3]);
        *(__half2*)(g_a2lo + o1)     = __halves2half2(l[0], l[1]);
        *(__half2*)(g_a2lo + o1 + 2) = __halves2half2(l[2], l[3]);
    }
}

// ================= mma.sync fp16 split GEMM (NN = block N, TERMS = 2 or 3) =================
#define ROWB 80

__device__ __forceinline__ uint32_t smem_u32(const void* p) {
    uint32_t a;
    asm("{ .reg .u64 t; cvta.to.shared.u64 t, %1; cvt.u32.u64 %0, t; }" : "=r"(a) : "l"(p));
    return a;
}
__device__ __forceinline__ void cp16(uint32_t s, const void* g) {
    asm volatile("cp.async.cg.shared.global [%0], [%1], 16;" :: "r"(s), "l"(g));
}
__device__ __forceinline__ void cp_commit() { asm volatile("cp.async.commit_group;"); }
__device__ __forceinline__ void cp_wait1() { asm volatile("cp.async.wait_group 1;"); }
__device__ __forceinline__ void ldm4(uint32_t* r, uint32_t a) {
    asm volatile("ldmatrix.sync.aligned.m8n8.x4.shared.b16 {%0,%1,%2,%3}, [%4];"
                 : "=r"(r[0]), "=r"(r[1]), "=r"(r[2]), "=r"(r[3]) : "r"(a));
}
__device__ __forceinline__ void mma_f16(float* c, const uint32_t* a, uint32_t b0, uint32_t b1) {
    asm volatile("mma.sync.aligned.m16n8k16.row.col.f32.f16.f16.f32 "
                 "{%0,%1,%2,%3},{%4,%5,%6,%7},{%8,%9},{%0,%1,%2,%3};"
                 : "+f"(c[0]), "+f"(c[1]), "+f"(c[2]), "+f"(c[3])
                 : "r"(a[0]), "r"(a[1]), "r"(a[2]), "r"(a[3]), "r"(b0), "r"(b1));
}

template <int NN, int TERMS>
__device__ __forceinline__ void gemm_mainloop(
    uint32_t smb, int tid, int w, int lane, int m0, int M, int K,
    const __half* ahi, const __half* alo,
    const __half* whi, const __half* wlo,
    float acc[2][2 * (NN / 32)][4])
{
    constexpr int NJ = NN / 32;
    constexpr int NBI = NN / 64;
    constexpr int SAHI = 0;
    constexpr int SALO = 128 * ROWB;
    constexpr int SBHI = 256 * ROWB;
    constexpr int SBLO = (256 + NN) * ROWB;  // used only if TERMS==3
    constexpr int BUF = (256 + (TERMS == 3 ? 2 : 1) * NN) * ROWB;

    int wm = (w >> 1) * 32;
    int wn = (w & 1) * (NN / 2);
    int arow = tid >> 2;
    int aseg = (tid & 3) * 16;
    int asegk = (tid & 3) * 8;
    int chunks = K >> 5;

    auto load_chunk = [&](int c) {
        int k0 = c * 32;
        uint32_t base = smb + (c & 1) * BUF;
        #pragma unroll
        for (int i = 0; i < 2; i++) {
            int row = arow + i * 64;
            int gr = m0 + row; if (gr >= M) gr = M - 1;
            size_t go = (size_t)gr * K + k0 + asegk;
            uint32_t so = row * ROWB + aseg;
            cp16(base + SAHI + so, ahi + go);
            cp16(base + SALO + so, alo + go);
        }
        #pragma unroll
        for (int i = 0; i < NBI; i++) {
            int row = arow + i * 64;
            size_t go = (size_t)row * K + k0 + asegk;
            uint32_t so = row * ROWB + aseg;
            cp16(base + SBHI + so, whi + go);
            if (TERMS == 3) cp16(base + SBLO + so, wlo + go);
        }
    };

    int grp = lane >> 3, lr = lane & 7;
    int a_row_off = lr + (grp & 1) * 8;
    int a_k_off = (grp >> 1) * 8;
    int b_row_off = (grp & 2) * 4 + lr;
    int b_k_off = (grp & 1) * 8;

    load_chunk(0);
    cp_commit();

    #pragma unroll 1
    for (int c = 0; c < chunks; c++) {
        if (c + 1 < chunks) load_chunk(c + 1);
        cp_commit();
        cp_wait1();
        __syncthreads();

        uint32_t base = smb + (c & 1) * BUF;
        #pragma unroll
        for (int s = 0; s < 2; s++) {
            uint32_t ah[2][4], al[2][4];
            #pragma unroll
            for (int mt = 0; mt < 2; mt++) {
                uint32_t ra = (wm + mt * 16 + a_row_off) * ROWB + (s * 16 + a_k_off) * 2;
                ldm4(ah[mt], base + SAHI + ra);
                ldm4(al[mt], base + SALO + ra);
            }
            #pragma unroll
            for (int j = 0; j < NJ; j++) {
                uint32_t rb = (wn + j * 16 + b_row_off) * ROWB + (s * 16 + b_k_off) * 2;
                uint32_t bh[4];
                ldm4(bh, base + SBHI + rb);
                #pragma unroll
                for (int mt = 0; mt < 2; mt++) {
                    mma_f16(acc[mt][2 * j],     ah[mt], bh[0], bh[1]);
                    mma_f16(acc[mt][2 * j],     al[mt], bh[0], bh[1]);
                    mma_f16(acc[mt][2 * j + 1], ah[mt], bh[2], bh[3]);
                    mma_f16(acc[mt][2 * j + 1], al[mt], bh[2], bh[3]);
                }
                if (TERMS == 3) {
                    uint32_t bl[4];
                    ldm4(bl, base + SBLO + rb);
                    #pragma unroll
                    for (int mt = 0; mt < 2; mt++) {
                        mma_f16(acc[mt][2 * j],     ah[mt], bl[0], bl[1]);
                        mma_f16(acc[mt][2 * j + 1], ah[mt], bl[2], bl[3]);
                    }
                }
            }
        }
        __syncthreads();
    }
}

template <int NN, int TERMS>
__global__ __launch_bounds__(256) void mmagemm_kernel(
    const __half* __restrict__ ahi, const __half* __restrict__ alo,
    const __half* __restrict__ whi, const __half* __restrict__ wlo,
    const float* __restrict__ bias, int M, int K,
    float* __restrict__ Cf32, int relu_f32,
    __half* __restrict__ shi, __half* __restrict__ slo,
    int s_lda, int s_col0, int s_maxrow)
{
    extern __shared__ char sm[];
    uint32_t smb = smem_u32(sm);
    int tid = threadIdx.x;
    int w = tid >> 5, lane = tid & 31;
    int m0 = blockIdx.x * 128;
    int wm = (w >> 1) * 32;
    int wn = (w & 1) * (NN / 2);

    float acc[2][2 * (NN / 32)][4];
    #pragma unroll
    for (int i = 0; i < 2; i++)
        #pragma unroll
        for (int j = 0; j < 2 * (NN / 32); j++)
            #pragma unroll
            for (int k = 0; k < 4; k++) acc[i][j][k] = 0.f;

    gemm_mainloop<NN, TERMS>(smb, tid, w, lane, m0, M, K, ahi, alo, whi, wlo, acc);

    int g = lane >> 2, t = lane & 3;
    #pragma unroll
    for (int mt = 0; mt < 2; mt++) {
        int r0 = m0 + wm + mt * 16 + g;
        #pragma unroll
        for (int j = 0; j < 2 * (NN / 32); j++) {
            int col = wn + j * 8 + 2 * t;
            float2 bv = *(const float2*)(bias + col);
            float o0 = acc[mt][j][0] + bv.x, o1 = acc[mt][j][1] + bv.y;
            float o2 = acc[mt][j][2] + bv.x, o3 = acc[mt][j][3] + bv.y;
            if (Cf32) {
                float p0 = o0, p1 = o1, p2 = o2, p3 = o3;
                if (relu_f32) {
                    p0 = fmaxf(p0, 0.f); p1 = fmaxf(p1, 0.f);
                    p2 = fmaxf(p2, 0.f); p3 = fmaxf(p3, 0.f);
                }
                if (r0 < M)     *(float2*)(Cf32 + (size_t)r0 * NN + col)       = make_float2(p0, p1);
                if (r0 + 8 < M) *(float2*)(Cf32 + (size_t)(r0 + 8) * NN + col) = make_float2(p2, p3);
            }
            if (shi) {
                o0 = fmaxf(o0, 0.f); o1 = fmaxf(o1, 0.f);
                o2 = fmaxf(o2, 0.f); o3 = fmaxf(o3, 0.f);
                __half h0, h1, h2, h3, l0, l1, l2, l3;
                split1(o0, h0, l0); split1(o1, h1, l1);
                split1(o2, h2, l2); split1(o3, h3, l3);
                if (r0 < s_maxrow) {
                    size_t o = (size_t)r0 * s_lda + s_col0 + col;
                    *(__half2*)(shi + o) = __halves2half2(h0, h1);
                    *(__half2*)(slo + o) = __halves2half2(l0, l1);
                }
                if (r0 + 8 < s_maxrow) {
                    size_t o = (size_t)(r0 + 8) * s_lda + s_col0 + col;
                    *(__half2*)(shi + o) = __halves2half2(h2, h3);
                    *(__half2*)(slo + o) = __halves2half2(l2, l3);
                }
            }
        }
    }
}

// ============ gemm (NN=128, TERMS=3) fused with log_softmax epilogue ============
__global__ __launch_bounds__(256) void gemm_softmax_kernel(
    const __half* __restrict__ ahi, const __half* __restrict__ alo,
    const __half* __restrict__ whi, const __half* __restrict__ wlo,
    const float* __restrict__ bias, int M, int K,
    float* __restrict__ out)
{
    extern __shared__ char sm[];
    uint32_t smb = smem_u32(sm);
    int tid = threadIdx.x;
    int w = tid >> 5, lane = tid & 31;
    int m0 = blockIdx.x * 128;
    int wm = (w >> 1) * 32;
    int wn = (w & 1) * 64;

    float acc[2][8][4];
    #pragma unroll
    for (int i = 0; i < 2; i++)
        #pragma unroll
        for (int j = 0; j < 8; j++)
            #pragma unroll
            for (int k = 0; k < 4; k++) acc[i][j][k] = 0.f;

    gemm_mainloop<128, 3>(smb, tid, w, lane, m0, M, K, ahi, alo, whi, wlo, acc);

    float* es = (float*)sm;
    int g = lane >> 2, t = lane & 3;
    #pragma unroll
    for (int mt = 0; mt < 2; mt++) {
        int r = wm + mt * 16 + g;
        #pragma unroll
        for (int j = 0; j < 8; j++) {
            int col = wn + j * 8 + 2 * t;
            float2 bv = *(const float2*)(bias + col);
            *(float2*)&es[(r)     * 132 + col] = make_float2(acc[mt][j][0] + bv.x, acc[mt][j][1] + bv.y);
            *(float2*)&es[(r + 8) * 132 + col] = make_float2(acc[mt][j][2] + bv.x, acc[mt][j][3] + bv.y);
        }
    }
    __syncthreads();

    for (int rr = 0; rr < 16; rr++) {
        int r = w * 16 + rr;
        int gr = m0 + r;
        if (gr >= M) break;
        float4 v = *(float4*)&es[r * 132 + lane * 4];
        float m = fmaxf(fmaxf(v.x, v.y), fmaxf(v.z, v.w));
        #pragma unroll
        for (int o = 16; o > 0; o >>= 1) m = fmaxf(m, __shfl_xor_sync(0xFFFFFFFFu, m, o));
        float s = expf(v.x - m) + expf(v.y - m) + expf(v.z - m) + expf(v.w - m);
        #pragma unroll
        for (int o = 16; o > 0; o >>= 1) s += __shfl_xor_sync(0xFFFFFFFFu, s, o);
        float l = m + logf(s);
        *(float4*)(out + (size_t)gr * F_OUT + lane * 4) =
            make_float4(v.x - l, v.y - l, v.z - l, v.w - l);
    }
}

// ---------------- launch ----------------
extern "C" void kernel_launch(void* const* d_in, const int* in_sizes, int n_in,
                              void* d_out, int out_size) {
    const float* x   = (const float*)d_in[0];
    const int*   ei1 = (const int*)d_in[1];
    const int*   ei2 = (const int*)d_in[2];
    const float* Wl1 = (const float*)d_in[3];
    const float* bl1 = (const float*)d_in[4];
    const float* Wr1 = (const float*)d_in[5];
    const float* Wl2 = (const float*)d_in[6];
    const float* bl2 = (const float*)d_in[7];
    const float* Wr2 = (const float*)d_in[8];
    const float* W1  = (const float*)d_in[9];
    const float* b1  = (const float*)d_in[10];
    const float* W2  = (const float*)d_in[11];
    const float* b2  = (const float*)d_in[12];

    float* out = (float*)d_out;
    float* out_ls  = out;                           // [10000,128]
    float* out_emb = out + (size_t)N_TGT2 * F_OUT;  // [10000,192]

    float* h1;
    __half *ahi, *alo, *whi;
    __half *a2hi, *a2lo, *w2hi, *w2lo;
    __half *a3hi, *a3lo, *w3hi, *w3lo;
    __half *a4hi, *a4lo, *w4hi, *w4lo;
    cudaGetSymbolAddress((void**)&h1, g_h1);
    cudaGetSymbolAddress((void**)&ahi, g_ahi);
    cudaGetSymbolAddress((void**)&alo, g_alo);
    cudaGetSymbolAddress((void**)&whi, g_whi);
    cudaGetSymbolAddress((void**)&a2hi, g_a2hi);
    cudaGetSymbolAddress((void**)&a2lo, g_a2lo);
    cudaGetSymbolAddress((void**)&w2hi, g_w2hi);
    cudaGetSymbolAddress((void**)&w2lo, g_w2lo);
    cudaGetSymbolAddress((void**)&a3hi, g_a3hi);
    cudaGetSymbolAddress((void**)&a3lo, g_a3lo);
    cudaGetSymbolAddress((void**)&w3hi, g_w3hi);
    cudaGetSymbolAddress((void**)&w3lo, g_w3lo);
    cudaGetSymbolAddress((void**)&a4hi, g_a4hi);
    cudaGetSymbolAddress((void**)&a4lo, g_a4lo);
    cudaGetSymbolAddress((void**)&w4hi, g_w4hi);
    cudaGetSymbolAddress((void**)&w4lo, g_w4lo);

    const int SMEM192_2 = 2 * (256 + 192) * ROWB;      // 71680
    const int SMEM192_3 = 2 * (256 + 2 * 192) * ROWB;  // 102400
    const int SMEM128_3 = 2 * (256 + 2 * 128) * ROWB;  // 81920 (>= 128*132*4 for softmax stage)
    cudaFuncSetAttribute((const void*)mmagemm_kernel<192, 2>, cudaFuncAttributeMaxDynamicSharedMemorySize, SMEM192_2);
    cudaFuncSetAttribute((const void*)mmagemm_kernel<192, 3>, cudaFuncAttributeMaxDynamicSharedMemorySize, SMEM192_3);
    cudaFuncSetAttribute((const void*)gemm_softmax_kernel, cudaFuncAttributeMaxDynamicSharedMemorySize, SMEM128_3);

    int nb1 = (N_TGT1 + 511) / 512;  // 98
    int nb2 = (N_TGT2 + 511) / 512;  // 20

    // 1: all converts + zero
    conv_all_kernel<<<(XQ + 58368 + 255) / 256, 256>>>(x, Wl1, Wr1, Wl2, Wr2, W1, W2);
    // 2-4: CSR build
    hist_both_kernel<<<((E1 + E2) / 4 + 255) / 256, 256>>>(ei1, ei2);
    scan_block_both_kernel<<<nb1 + nb2, 512>>>(nb1);
    fill_both_kernel<<<((E1 + E2) / 4 + 255) / 256, 256>>>(ei1, ei2);

    // 5: layer-1 aggregation
    agg1_kernel<<<(N_TGT1 * 2 * 32 + 255) / 256, 256>>>(x);

    // 6: layer-1 GEMM (2-term) -> h1 fp32 (relu) + h1 split rows<10000
    mmagemm_kernel<192, 2><<<(N_TGT1 + 127) / 128, 256, SMEM192_2>>>(
        ahi, alo, whi, (const __half*)0, bl1, N_TGT1, 512,
        h1, 1,
        a2hi, a2lo, 384, 192, N_TGT2);

    // 7: layer-2 aggregation
    agg2_kernel<<<(N_TGT2 * 32 + 255) / 256, 256>>>(h1);

    // 8: layer-2 GEMM (3-term) -> h2 split
    mmagemm_kernel<192, 3><<<(N_TGT2 + 127) / 128, 256, SMEM192_3>>>(
        a2hi, a2lo, w2hi, w2lo, bl2, N_TGT2, 384,
        (float*)0, 0,
        a3hi, a3lo, 192, 0, N_TGT2);

    // 9: layer-3 GEMM (3-term) -> embedding fp32 + relu(emb) split
    mmagemm_kernel<192, 3><<<(N_TGT2 + 127) / 128, 256, SMEM192_3>>>(
        a3hi, a3lo, w3hi, w3lo, b1, N_TGT2, 192,
        out_emb, 0,
        a4hi, a4lo, 192, 0, N_TGT2);

    // 10: layer-4 GEMM (3-term) + log_softmax -> out_ls
    gemm_softmax_kernel<<<(N_TGT2 + 127) / 128, 256, SMEM128_3>>>(
        a4hi, a4lo, w4hi, w4lo, b2, N_TGT2, 192, out_ls);
}